// round 1
// baseline (speedup 1.0000x reference)
#include <cuda_runtime.h>
#include <cuda_bf16.h>
#include <math.h>

// Problem constants
#define BATCH 8
#define SEQ   2048
#define DIM   512
#define KDIM  1024          // N*D concat feature dim
#define MTOT  (BATCH*SEQ)   // 16384

// Scratch for q, k, v (no cudaMalloc allowed)
__device__ float g_q[MTOT * DIM];
__device__ float g_k[MTOT * DIM];
__device__ float g_v[MTOT * DIM];

// ---------------------------------------------------------------------------
// Fused QKV GEMM: C[m,n] = sum_k x[m,k] * W[k,n]
//   x[m,k] = (k<512) ? x0[m*512+k] : x1[m*512+k-512]
//   blockIdx.z selects (Wq->g_q scaled by 1/sqrt(D)), (Wk->g_k), (Wv->g_v)
// Tiles: BM=128, BN=64, BK=16, 256 threads, 8x4 micro-tile per thread.
// ---------------------------------------------------------------------------
__global__ __launch_bounds__(256)
void qkv_gemm(const float* __restrict__ x0, const float* __restrict__ x1,
              const float* __restrict__ Wq, const float* __restrict__ Wk,
              const float* __restrict__ Wv)
{
    __shared__ float AsT[16 * 132];   // [k][m], stride 132 (pad 4, 16B aligned)
    __shared__ float Bs[16][64];      // [k][n]

    const int z = blockIdx.z;
    const float* __restrict__ W = (z == 0) ? Wq : ((z == 1) ? Wk : Wv);
    float* __restrict__ C = (z == 0) ? g_q : ((z == 1) ? g_k : g_v);

    const int m0 = blockIdx.y * 128;
    const int n0 = blockIdx.x * 64;
    const int tid = threadIdx.x;
    const int tx = tid & 15;          // 16 n-groups of 4
    const int ty = tid >> 4;          // 16 m-groups of 8

    float acc[8][4];
#pragma unroll
    for (int i = 0; i < 8; i++)
#pragma unroll
        for (int j = 0; j < 4; j++) acc[i][j] = 0.0f;

    const int b_row = tid >> 4;       // 0..15
    const int b_c4  = tid & 15;       // 0..15 (float4 col)

    for (int k0 = 0; k0 < KDIM; k0 += 16) {
        // Load A tile: 128 rows x 16 k  (2 float4 per thread), store K-transposed
#pragma unroll
        for (int r = 0; r < 2; r++) {
            int f = tid + r * 256;
            int a_row = f >> 2;               // 0..127
            int a_c4  = f & 3;                // float4 within 16-k chunk
            int kk = k0 + a_c4 * 4;
            const float* src = (kk < 512)
                ? (x0 + (size_t)(m0 + a_row) * 512 + kk)
                : (x1 + (size_t)(m0 + a_row) * 512 + (kk - 512));
            float4 av = *(const float4*)src;
            AsT[(a_c4 * 4 + 0) * 132 + a_row] = av.x;
            AsT[(a_c4 * 4 + 1) * 132 + a_row] = av.y;
            AsT[(a_c4 * 4 + 2) * 132 + a_row] = av.z;
            AsT[(a_c4 * 4 + 3) * 132 + a_row] = av.w;
        }
        // Load B tile: 16 rows x 64 n (1 float4 per thread)
        {
            float4 bv = *(const float4*)(W + (size_t)(k0 + b_row) * 512 + n0 + b_c4 * 4);
            *(float4*)&Bs[b_row][b_c4 * 4] = bv;
        }
        __syncthreads();

#pragma unroll
        for (int kk = 0; kk < 16; kk++) {
            float4 a0 = *(const float4*)(AsT + kk * 132 + ty * 8);
            float4 a1 = *(const float4*)(AsT + kk * 132 + ty * 8 + 4);
            float4 bv = *(const float4*)(&Bs[kk][tx * 4]);
            float a[8] = {a0.x, a0.y, a0.z, a0.w, a1.x, a1.y, a1.z, a1.w};
            float bb[4] = {bv.x, bv.y, bv.z, bv.w};
#pragma unroll
            for (int i = 0; i < 8; i++)
#pragma unroll
                for (int j = 0; j < 4; j++)
                    acc[i][j] += a[i] * bb[j];
        }
        __syncthreads();
    }

    const float scale = (z == 0) ? 0.04419417382415922f : 1.0f;  // 1/sqrt(512) fused into q
#pragma unroll
    for (int i = 0; i < 8; i++) {
        float4 o;
        o.x = acc[i][0] * scale;
        o.y = acc[i][1] * scale;
        o.z = acc[i][2] * scale;
        o.w = acc[i][3] * scale;
        *(float4*)(C + (size_t)(m0 + ty * 8 + i) * 512 + n0 + tx * 4) = o;
    }
}

// ---------------------------------------------------------------------------
// Flash attention + fused LayerNorm.
// Block = (batch b, query tile qb of 32 rows). 256 threads.
// Smem: Qs/Ks/Vs [32][513] fp32 (pad 1 -> conflict-free scalar reads),
//       Ps [32][33], sm_alpha[32], sm_l[32].
// Mapping A (S/softmax): 16x16 thread grid, 2x2 S micro-tile.
// Mapping B (O update / epilogue): i = tid>>3 (row), g = tid&7; O[64] regs,
//       d = g + 8c.
// ---------------------------------------------------------------------------
#define ROW_STRIDE 513
#define NEG_INF __int_as_float(0xff800000)

__global__ __launch_bounds__(256)
void attn_kernel(const float* __restrict__ gamma, const float* __restrict__ beta,
                 float* __restrict__ out)
{
    extern __shared__ float smem[];
    float* Qs = smem;                           // 32*513
    float* Ks = Qs + 32 * ROW_STRIDE;
    float* Vs = Ks + 32 * ROW_STRIDE;
    float* Ps = Vs + 32 * ROW_STRIDE;           // 32*33
    float* sm_al = Ps + 32 * 33;                // 32
    float* sm_l  = sm_al + 32;                  // 32

    const int b  = blockIdx.y;
    const int qb = blockIdx.x;
    const int tid = threadIdx.x;

    // Mapping A indices
    const int ti = tid >> 4;     // 0..15 -> rows 2ti, 2ti+1
    const int tj = tid & 15;     // 0..15 -> cols 2tj, 2tj+1
    // Mapping B indices
    const int iB = tid >> 3;     // 0..31 row
    const int gB = tid & 7;      // 0..7  d-phase

    const float* __restrict__ Qg = g_q + ((size_t)b * SEQ + (size_t)qb * 32) * DIM;

    // Load Q tile (already pre-scaled by 1/sqrt(D) in the GEMM)
    for (int f = tid; f < 32 * 128; f += 256) {
        int row = f >> 7, c4 = f & 127;
        float4 v = *(const float4*)(Qg + (size_t)row * DIM + c4 * 4);
        float* dst = Qs + row * ROW_STRIDE + c4 * 4;
        dst[0] = v.x; dst[1] = v.y; dst[2] = v.z; dst[3] = v.w;
    }

    float Oacc[64];
#pragma unroll
    for (int c = 0; c < 64; c++) Oacc[c] = 0.0f;

    // Online-softmax state, register-resident (uniform across each 16-lane row group)
    float m0r = NEG_INF, m1r = NEG_INF;
    float l0r = 0.0f,    l1r = 0.0f;

    __syncthreads();

    for (int jb = 0; jb <= qb; jb++) {
        // ---- load K, V tiles ----
        const float* __restrict__ Kg = g_k + ((size_t)b * SEQ + (size_t)jb * 32) * DIM;
        const float* __restrict__ Vg = g_v + ((size_t)b * SEQ + (size_t)jb * 32) * DIM;
        for (int f = tid; f < 32 * 128; f += 256) {
            int row = f >> 7, c4 = f & 127;
            float4 kv = *(const float4*)(Kg + (size_t)row * DIM + c4 * 4);
            float4 vv = *(const float4*)(Vg + (size_t)row * DIM + c4 * 4);
            float* kd = Ks + row * ROW_STRIDE + c4 * 4;
            kd[0] = kv.x; kd[1] = kv.y; kd[2] = kv.z; kd[3] = kv.w;
            float* vd = Vs + row * ROW_STRIDE + c4 * 4;
            vd[0] = vv.x; vd[1] = vv.y; vd[2] = vv.z; vd[3] = vv.w;
        }
        __syncthreads();

        // ---- S = Q K^T (2x2 per thread) ----
        float s00 = 0.f, s01 = 0.f, s10 = 0.f, s11 = 0.f;
        {
            const float* q0 = Qs + (2 * ti) * ROW_STRIDE;
            const float* q1 = q0 + ROW_STRIDE;
            const float* k0 = Ks + (2 * tj) * ROW_STRIDE;
            const float* k1 = k0 + ROW_STRIDE;
#pragma unroll 8
            for (int d = 0; d < DIM; d++) {
                float a0 = q0[d], a1 = q1[d];
                float b0 = k0[d], b1 = k1[d];
                s00 += a0 * b0; s01 += a0 * b1;
                s10 += a1 * b0; s11 += a1 * b1;
            }
        }

        // ---- causal mask (only needed on the diagonal block) ----
        if (jb == qb) {
            int qi0 = qb * 32 + 2 * ti;
            int kj0 = jb * 32 + 2 * tj;
            if (kj0     > qi0)     s00 = NEG_INF;
            if (kj0 + 1 > qi0)     s01 = NEG_INF;
            if (kj0     > qi0 + 1) s10 = NEG_INF;
            if (kj0 + 1 > qi0 + 1) s11 = NEG_INF;
        }

        // ---- row max over the 16-lane group ----
        float r0 = fmaxf(s00, s01);
        float r1 = fmaxf(s10, s11);
#pragma unroll
        for (int off = 1; off < 16; off <<= 1) {
            r0 = fmaxf(r0, __shfl_xor_sync(0xffffffffu, r0, off));
            r1 = fmaxf(r1, __shfl_xor_sync(0xffffffffu, r1, off));
        }

        float mn0 = fmaxf(m0r, r0);
        float mn1 = fmaxf(m1r, r1);
        float al0 = __expf(m0r - mn0);   // 0 on first block (exp(-inf))
        float al1 = __expf(m1r - mn1);

        float p00 = __expf(s00 - mn0), p01 = __expf(s01 - mn0);
        float p10 = __expf(s10 - mn1), p11 = __expf(s11 - mn1);

        float rs0 = p00 + p01;
        float rs1 = p10 + p11;
#pragma unroll
        for (int off = 1; off < 16; off <<= 1) {
            rs0 += __shfl_xor_sync(0xffffffffu, rs0, off);
            rs1 += __shfl_xor_sync(0xffffffffu, rs1, off);
        }
        l0r = al0 * l0r + rs0;  m0r = mn0;
        l1r = al1 * l1r + rs1;  m1r = mn1;

        if (tj == 0) {
            sm_al[2 * ti]     = al0;
            sm_al[2 * ti + 1] = al1;
            sm_l [2 * ti]     = l0r;
            sm_l [2 * ti + 1] = l1r;
        }
        Ps[(2 * ti)     * 33 + 2 * tj]     = p00;
        Ps[(2 * ti)     * 33 + 2 * tj + 1] = p01;
        Ps[(2 * ti + 1) * 33 + 2 * tj]     = p10;
        Ps[(2 * ti + 1) * 33 + 2 * tj + 1] = p11;
        __syncthreads();

        // ---- O = alpha*O + P @ V ----
        {
            float alpha = sm_al[iB];
#pragma unroll
            for (int c = 0; c < 64; c++) Oacc[c] *= alpha;
            const float* Prow = Ps + iB * 33;
            const float* vbase = Vs + gB;
#pragma unroll 2
            for (int j = 0; j < 32; j++) {
                float p = Prow[j];
                const float* vrow = vbase + j * ROW_STRIDE;
#pragma unroll
                for (int c = 0; c < 64; c++)
                    Oacc[c] += p * vrow[c * 8];
            }
        }
        __syncthreads();
    }

    // ---- epilogue: normalize by l, LayerNorm over D, write out ----
    {
        float linv = 1.0f / sm_l[iB];
        float sum = 0.0f, sq = 0.0f;
#pragma unroll
        for (int c = 0; c < 64; c++) {
            Oacc[c] *= linv;
            sum += Oacc[c];
            sq  += Oacc[c] * Oacc[c];
        }
#pragma unroll
        for (int off = 1; off < 8; off <<= 1) {
            sum += __shfl_xor_sync(0xffffffffu, sum, off);
            sq  += __shfl_xor_sync(0xffffffffu, sq,  off);
        }
        const float invD = 1.0f / (float)DIM;
        float mu  = sum * invD;
        float var = sq * invD - mu * mu;
        float rstd = rsqrtf(var + 1e-5f);

        size_t base = ((size_t)b * SEQ + (size_t)qb * 32 + iB) * DIM;
#pragma unroll
        for (int c = 0; c < 64; c++) {
            int d = gB + 8 * c;
            out[base + d] = (Oacc[c] - mu) * rstd * gamma[d] + beta[d];
        }
    }
}

// ---------------------------------------------------------------------------
// Launch
// ---------------------------------------------------------------------------
extern "C" void kernel_launch(void* const* d_in, const int* in_sizes, int n_in,
                              void* d_out, int out_size)
{
    const float* x0    = (const float*)d_in[0];
    const float* x1    = (const float*)d_in[1];
    const float* Wq    = (const float*)d_in[2];
    const float* Wk    = (const float*)d_in[3];
    const float* Wv    = (const float*)d_in[4];
    const float* gamma = (const float*)d_in[5];
    const float* beta  = (const float*)d_in[6];
    float* out = (float*)d_out;

    const int smem_bytes = (3 * 32 * ROW_STRIDE + 32 * 33 + 64) * (int)sizeof(float);
    cudaFuncSetAttribute(attn_kernel, cudaFuncAttributeMaxDynamicSharedMemorySize, smem_bytes);

    // QKV projection (z = 0:q, 1:k, 2:v)
    qkv_gemm<<<dim3(DIM / 64, MTOT / 128, 3), 256>>>(x0, x1, Wq, Wk, Wv);

    // Attention + LayerNorm
    attn_kernel<<<dim3(SEQ / 32, BATCH), 256, smem_bytes>>>(gamma, beta, out);
}

// round 3
// speedup vs baseline: 1.4396x; 1.4396x over previous
#include <cuda_runtime.h>
#include <cuda_bf16.h>
#include <math.h>

// Problem constants
#define BATCH 8
#define SEQ   2048
#define DIM   512
#define KDIM  1024          // N*D concat feature dim
#define MTOT  (BATCH*SEQ)   // 16384

// Scratch (no cudaMalloc allowed)
__device__ float g_q[MTOT * DIM];
__device__ float g_k[MTOT * DIM];
__device__ float g_v[MTOT * DIM];
__device__ __nv_bfloat16 g_Ah[(size_t)MTOT * KDIM];    // x concat, bf16 hi
__device__ __nv_bfloat16 g_Al[(size_t)MTOT * KDIM];    // x concat, bf16 lo
__device__ __nv_bfloat16 g_Wh[(size_t)3 * DIM * KDIM]; // W^T rows: [q|k|v] x 1024, hi
__device__ __nv_bfloat16 g_Wl[(size_t)3 * DIM * KDIM]; // lo

// ---------------------------------------------------------------------------
// helpers
// ---------------------------------------------------------------------------
__device__ __forceinline__ unsigned smem_u32(const void* p) {
    unsigned a;
    asm("{ .reg .u64 t; cvta.to.shared.u64 t, %1; cvt.u32.u64 %0, t; }" : "=r"(a) : "l"(p));
    return a;
}
__device__ __forceinline__ void cpa16(unsigned dst, const void* src) {
    asm volatile("cp.async.cg.shared.global [%0], [%1], 16;"
                 :: "r"(dst), "l"(__cvta_generic_to_global(src)) : "memory");
}
__device__ __forceinline__ void ldsm4(unsigned* r, unsigned addr) {
    asm volatile("ldmatrix.sync.aligned.m8n8.x4.shared.b16 {%0,%1,%2,%3}, [%4];"
                 : "=r"(r[0]), "=r"(r[1]), "=r"(r[2]), "=r"(r[3]) : "r"(addr));
}
__device__ __forceinline__ void mma_bf16(float* c, const unsigned* a,
                                         unsigned b0, unsigned b1) {
    asm volatile(
        "mma.sync.aligned.m16n8k16.row.col.f32.bf16.bf16.f32 "
        "{%0,%1,%2,%3}, {%4,%5,%6,%7}, {%8,%9}, {%0,%1,%2,%3};"
        : "+f"(c[0]), "+f"(c[1]), "+f"(c[2]), "+f"(c[3])
        : "r"(a[0]), "r"(a[1]), "r"(a[2]), "r"(a[3]), "r"(b0), "r"(b1));
}

// ---------------------------------------------------------------------------
// Conversion: x0|x1 -> bf16 hi/lo, row-major [MTOT][1024]
// ---------------------------------------------------------------------------
__global__ __launch_bounds__(256)
void conv_x(const float* __restrict__ x0, const float* __restrict__ x1)
{
    unsigned t = blockIdx.x * 256u + threadIdx.x;
    unsigned m  = t >> 8;
    unsigned k4 = (t & 255u) * 4u;
    float4 v = (k4 < 512u)
        ? *(const float4*)(x0 + (size_t)m * 512 + k4)
        : *(const float4*)(x1 + (size_t)m * 512 + (k4 - 512u));
    __nv_bfloat16 h0 = __float2bfloat16(v.x);
    __nv_bfloat16 h1 = __float2bfloat16(v.y);
    __nv_bfloat16 h2 = __float2bfloat16(v.z);
    __nv_bfloat16 h3 = __float2bfloat16(v.w);
    __nv_bfloat16 l0 = __float2bfloat16(v.x - __bfloat162float(h0));
    __nv_bfloat16 l1 = __float2bfloat16(v.y - __bfloat162float(h1));
    __nv_bfloat16 l2 = __float2bfloat16(v.z - __bfloat162float(h2));
    __nv_bfloat16 l3 = __float2bfloat16(v.w - __bfloat162float(h3));
    size_t o = (size_t)m * 1024 + k4;
    __nv_bfloat162* dh = (__nv_bfloat162*)(g_Ah + o);
    __nv_bfloat162* dl = (__nv_bfloat162*)(g_Al + o);
    dh[0] = __nv_bfloat162(h0, h1); dh[1] = __nv_bfloat162(h2, h3);
    dl[0] = __nv_bfloat162(l0, l1); dl[1] = __nv_bfloat162(l2, l3);
}

// ---------------------------------------------------------------------------
// Conversion: W[k][n] -> W^T hi/lo bf16, rows n-major (q scaled by 1/sqrt(D))
// ---------------------------------------------------------------------------
__global__ __launch_bounds__(256)
void conv_w(const float* __restrict__ Wq, const float* __restrict__ Wk,
            const float* __restrict__ Wv)
{
    __shared__ float tile[32][33];
    const int z  = blockIdx.z;
    const float* __restrict__ W = (z == 0) ? Wq : ((z == 1) ? Wk : Wv);
    const int n0 = blockIdx.x * 32;
    const int k0 = blockIdx.y * 32;
    const int tx = threadIdx.x;      // 0..31
    const int ty = threadIdx.y;      // 0..7

    for (int r = ty; r < 32; r += 8)
        tile[r][tx] = W[(size_t)(k0 + r) * 512 + n0 + tx];
    __syncthreads();

    const float scale = (z == 0) ? 0.04419417382415922f : 1.0f;
    for (int r = ty; r < 32; r += 8) {
        int n = n0 + r;
        int k = k0 + tx;
        float v = tile[tx][r] * scale;
        __nv_bfloat16 hi = __float2bfloat16(v);
        __nv_bfloat16 lo = __float2bfloat16(v - __bfloat162float(hi));
        size_t idx = ((size_t)(z * 512 + n)) * 1024 + k;
        g_Wh[idx] = hi;
        g_Wl[idx] = lo;
    }
}

// ---------------------------------------------------------------------------
// QKV GEMM via mma.sync bf16 split-2 (hi*hi + hi*lo + lo*hi).
// CTA tile M=128 x N=128, BK=32, 8 warps in 2x4 grid (warp tile 64x32).
// smem rows pitch 80B (odd multiple of 16B -> ldmatrix conflict-free).
// Double-buffered cp.async. grid = (1536/128=12, 16384/128=128).
// smem buffer: Ah[0,10240) Al[10240,20480) Bh[20480,30720) Bl[30720,40960)
// ---------------------------------------------------------------------------
#define GB_BUF 40960
#define GB_SMEM (2 * GB_BUF)

__device__ __forceinline__ void gemm_issue(unsigned sb, int buf, int m0, int nbase,
                                           int k0, int tid)
{
    const int lr  = tid >> 1;           // 0..127
    const int lc0 = (tid & 1) * 2;      // 0 or 2
    unsigned base = sb + buf * GB_BUF;
    const __nv_bfloat16* pa_h = g_Ah + (size_t)(m0 + lr) * 1024 + k0;
    const __nv_bfloat16* pa_l = g_Al + (size_t)(m0 + lr) * 1024 + k0;
    const __nv_bfloat16* pb_h = g_Wh + (size_t)(nbase + lr) * 1024 + k0;
    const __nv_bfloat16* pb_l = g_Wl + (size_t)(nbase + lr) * 1024 + k0;
#pragma unroll
    for (int cc = 0; cc < 2; cc++) {
        int c = lc0 + cc;
        unsigned o = lr * 80 + c * 16;
        cpa16(base + o,          pa_h + c * 8);
        cpa16(base + 10240 + o,  pa_l + c * 8);
        cpa16(base + 20480 + o,  pb_h + c * 8);
        cpa16(base + 30720 + o,  pb_l + c * 8);
    }
    asm volatile("cp.async.commit_group;" ::: "memory");
}

__global__ __launch_bounds__(256, 2)
void qkv_hmma()
{
    extern __shared__ char smem[];
    unsigned sb = smem_u32(smem);
    const int tid  = threadIdx.x;
    const int lane = tid & 31;
    const int w    = tid >> 5;
    const int wm   = w >> 2;        // 0..1
    const int wn   = w & 3;         // 0..3
    const int nbase = blockIdx.x * 128;
    const int m0    = blockIdx.y * 128;

    float acc[4][4][4];
#pragma unroll
    for (int i = 0; i < 4; i++)
#pragma unroll
        for (int j = 0; j < 4; j++)
#pragma unroll
            for (int k = 0; k < 4; k++) acc[i][j][k] = 0.0f;

    // ldmatrix lane address components
    const int mrowA = (lane & 7) + ((lane >> 3) & 1) * 8;  // 0..15
    const int kcA   = (lane >> 4) & 1;
    const int nrowB = (lane & 7) + ((lane >> 4) & 1) * 8;
    const int kcB   = (lane >> 3) & 1;
    const unsigned aoff = (wm * 64 + mrowA) * 80 + kcA * 16;
    const unsigned boff = 20480u + (wn * 32 + nrowB) * 80 + kcB * 16;

    gemm_issue(sb, 0, m0, nbase, 0, tid);

    for (int ch = 0; ch < 32; ++ch) {
        if (ch + 1 < 32) {
            gemm_issue(sb, (ch + 1) & 1, m0, nbase, (ch + 1) * 32, tid);
            asm volatile("cp.async.wait_group 1;" ::: "memory");
        } else {
            asm volatile("cp.async.wait_group 0;" ::: "memory");
        }
        __syncthreads();

        unsigned base = sb + (ch & 1) * GB_BUF;
#pragma unroll
        for (int ks = 0; ks < 2; ks++) {
            unsigned Bh[8], Bl[8];
            ldsm4(&Bh[0], base + boff + ks * 32);
            ldsm4(&Bh[4], base + boff + 16 * 80 + ks * 32);
            ldsm4(&Bl[0], base + boff + 10240 + ks * 32);
            ldsm4(&Bl[4], base + boff + 10240 + 16 * 80 + ks * 32);
#pragma unroll
            for (int mt = 0; mt < 4; mt++) {
                unsigned Ah[4], Al[4];
                ldsm4(Ah, base + aoff + mt * (16 * 80) + ks * 32);
                ldsm4(Al, base + aoff + 10240 + mt * (16 * 80) + ks * 32);
#pragma unroll
                for (int nt = 0; nt < 4; nt++) {
                    mma_bf16(acc[mt][nt], Ah, Bh[nt * 2], Bh[nt * 2 + 1]);
                    mma_bf16(acc[mt][nt], Ah, Bl[nt * 2], Bl[nt * 2 + 1]);
                    mma_bf16(acc[mt][nt], Al, Bh[nt * 2], Bh[nt * 2 + 1]);
                }
            }
        }
        __syncthreads();
    }

    // Epilogue: direct fp32 stores (float2 per c-pair)
    const int z = nbase >> 9;                 // 0:q 1:k 2:v
    float* Cout = (z == 0) ? g_q : ((z == 1) ? g_k : g_v);
    const int colb = (nbase & 511) + wn * 32;
    const int gid = lane >> 2, tig = lane & 3;
#pragma unroll
    for (int mt = 0; mt < 4; mt++) {
#pragma unroll
        for (int nt = 0; nt < 4; nt++) {
            int row = m0 + wm * 64 + mt * 16 + gid;
            int col = colb + nt * 8 + tig * 2;
            float2 v0 = make_float2(acc[mt][nt][0], acc[mt][nt][1]);
            float2 v1 = make_float2(acc[mt][nt][2], acc[mt][nt][3]);
            *(float2*)(Cout + (size_t)row * 512 + col)       = v0;
            *(float2*)(Cout + (size_t)(row + 8) * 512 + col) = v1;
        }
    }
}

// ---------------------------------------------------------------------------
// Flash attention + fused LayerNorm (SIMT fp32).
// Mapping A (S/softmax): 16x16 thread grid, 2x2 S micro-tile.
// Mapping B (O/epilogue): rp = tid>>4 owns rows {2rp, 2rp+1}; g = tid&15;
//   V loads depend only on (j, g) -> broadcast across halves, conflict-free.
// ---------------------------------------------------------------------------
#define ROW_STRIDE 513
#define NEG_INF __int_as_float(0xff800000)

__global__ __launch_bounds__(256)
void attn_kernel(const float* __restrict__ gamma, const float* __restrict__ beta,
                 float* __restrict__ out)
{
    extern __shared__ float smemf[];
    float* Qs = smemf;                          // 32*513
    float* Ks = Qs + 32 * ROW_STRIDE;
    float* Vs = Ks + 32 * ROW_STRIDE;
    float* Ps = Vs + 32 * ROW_STRIDE;           // 32*33
    float* sm_al = Ps + 32 * 33;                // 32
    float* sm_l  = sm_al + 32;                  // 32

    const int b  = blockIdx.y;
    const int qb = blockIdx.x;
    const int tid = threadIdx.x;

    const int ti = tid >> 4;
    const int tj = tid & 15;
    const int rp = tid >> 4;     // 0..15 -> rows 2rp, 2rp+1
    const int g  = tid & 15;     // d-phase

    const float* __restrict__ Qg = g_q + ((size_t)b * SEQ + (size_t)qb * 32) * DIM;

    for (int f = tid; f < 32 * 128; f += 256) {
        int row = f >> 7, c4 = f & 127;
        float4 v = *(const float4*)(Qg + (size_t)row * DIM + c4 * 4);
        float* dst = Qs + row * ROW_STRIDE + c4 * 4;
        dst[0] = v.x; dst[1] = v.y; dst[2] = v.z; dst[3] = v.w;
    }

    float Oacc[64];   // [2 rows][32 cols]
#pragma unroll
    for (int c = 0; c < 64; c++) Oacc[c] = 0.0f;

    float m0r = NEG_INF, m1r = NEG_INF;
    float l0r = 0.0f,    l1r = 0.0f;

    __syncthreads();

    for (int jb = 0; jb <= qb; jb++) {
        const float* __restrict__ Kg = g_k + ((size_t)b * SEQ + (size_t)jb * 32) * DIM;
        const float* __restrict__ Vg = g_v + ((size_t)b * SEQ + (size_t)jb * 32) * DIM;
        for (int f = tid; f < 32 * 128; f += 256) {
            int row = f >> 7, c4 = f & 127;
            float4 kv = *(const float4*)(Kg + (size_t)row * DIM + c4 * 4);
            float4 vv = *(const float4*)(Vg + (size_t)row * DIM + c4 * 4);
            float* kd = Ks + row * ROW_STRIDE + c4 * 4;
            kd[0] = kv.x; kd[1] = kv.y; kd[2] = kv.z; kd[3] = kv.w;
            float* vd = Vs + row * ROW_STRIDE + c4 * 4;
            vd[0] = vv.x; vd[1] = vv.y; vd[2] = vv.z; vd[3] = vv.w;
        }
        __syncthreads();

        // S = Q K^T (2x2 per thread)
        float s00 = 0.f, s01 = 0.f, s10 = 0.f, s11 = 0.f;
        {
            const float* q0 = Qs + (2 * ti) * ROW_STRIDE;
            const float* q1 = q0 + ROW_STRIDE;
            const float* k0 = Ks + (2 * tj) * ROW_STRIDE;
            const float* k1 = k0 + ROW_STRIDE;
#pragma unroll 8
            for (int d = 0; d < DIM; d++) {
                float a0 = q0[d], a1 = q1[d];
                float b0 = k0[d], b1 = k1[d];
                s00 += a0 * b0; s01 += a0 * b1;
                s10 += a1 * b0; s11 += a1 * b1;
            }
        }

        if (jb == qb) {
            int qi0 = qb * 32 + 2 * ti;
            int kj0 = jb * 32 + 2 * tj;
            if (kj0     > qi0)     s00 = NEG_INF;
            if (kj0 + 1 > qi0)     s01 = NEG_INF;
            if (kj0     > qi0 + 1) s10 = NEG_INF;
            if (kj0 + 1 > qi0 + 1) s11 = NEG_INF;
        }

        float r0 = fmaxf(s00, s01);
        float r1 = fmaxf(s10, s11);
#pragma unroll
        for (int off = 1; off < 16; off <<= 1) {
            r0 = fmaxf(r0, __shfl_xor_sync(0xffffffffu, r0, off));
            r1 = fmaxf(r1, __shfl_xor_sync(0xffffffffu, r1, off));
        }

        float mn0 = fmaxf(m0r, r0);
        float mn1 = fmaxf(m1r, r1);
        float al0 = __expf(m0r - mn0);
        float al1 = __expf(m1r - mn1);

        float p00 = __expf(s00 - mn0), p01 = __expf(s01 - mn0);
        float p10 = __expf(s10 - mn1), p11 = __expf(s11 - mn1);

        float rs0 = p00 + p01;
        float rs1 = p10 + p11;
#pragma unroll
        for (int off = 1; off < 16; off <<= 1) {
            rs0 += __shfl_xor_sync(0xffffffffu, rs0, off);
            rs1 += __shfl_xor_sync(0xffffffffu, rs1, off);
        }
        l0r = al0 * l0r + rs0;  m0r = mn0;
        l1r = al1 * l1r + rs1;  m1r = mn1;

        if (tj == 0) {
            sm_al[2 * ti]     = al0;
            sm_al[2 * ti + 1] = al1;
            sm_l [2 * ti]     = l0r;
            sm_l [2 * ti + 1] = l1r;
        }
        Ps[(2 * ti)     * 33 + 2 * tj]     = p00;
        Ps[(2 * ti)     * 33 + 2 * tj + 1] = p01;
        Ps[(2 * ti + 1) * 33 + 2 * tj]     = p10;
        Ps[(2 * ti + 1) * 33 + 2 * tj + 1] = p11;
        __syncthreads();

        // O = alpha*O + P @ V  (2 rows x 32 d per thread)
        {
            float a0 = sm_al[2 * rp];
            float a1 = sm_al[2 * rp + 1];
#pragma unroll
            for (int c = 0; c < 32; c++) { Oacc[c] *= a0; Oacc[32 + c] *= a1; }
            const float* P0 = Ps + (2 * rp) * 33;
            const float* P1 = P0 + 33;
            const float* vb = Vs + g;
#pragma unroll 2
            for (int j = 0; j < 32; j++) {
                float p0 = P0[j], p1 = P1[j];
                const float* vr = vb + j * ROW_STRIDE;
#pragma unroll
                for (int c = 0; c < 32; c++) {
                    float v = vr[c * 16];
                    Oacc[c]      += p0 * v;
                    Oacc[32 + c] += p1 * v;
                }
            }
        }
        __syncthreads();
    }

    // Epilogue: softmax normalize + LayerNorm + write
    {
        float linv0 = 1.0f / sm_l[2 * rp];
        float linv1 = 1.0f / sm_l[2 * rp + 1];
        float s0 = 0.f, q0 = 0.f, s1 = 0.f, q1 = 0.f;
#pragma unroll
        for (int c = 0; c < 32; c++) {
            Oacc[c] *= linv0;       s0 += Oacc[c];      q0 += Oacc[c] * Oacc[c];
            Oacc[32 + c] *= linv1;  s1 += Oacc[32 + c]; q1 += Oacc[32 + c] * Oacc[32 + c];
        }
#pragma unroll
        for (int off = 1; off < 16; off <<= 1) {
            s0 += __shfl_xor_sync(0xffffffffu, s0, off);
            q0 += __shfl_xor_sync(0xffffffffu, q0, off);
            s1 += __shfl_xor_sync(0xffffffffu, s1, off);
            q1 += __shfl_xor_sync(0xffffffffu, q1, off);
        }
        const float invD = 1.0f / (float)DIM;
        float mu0 = s0 * invD, var0 = q0 * invD - mu0 * mu0;
        float mu1 = s1 * invD, var1 = q1 * invD - mu1 * mu1;
        float rstd0 = rsqrtf(var0 + 1e-5f);
        float rstd1 = rsqrtf(var1 + 1e-5f);

        size_t base0 = ((size_t)b * SEQ + (size_t)qb * 32 + 2 * rp) * DIM;
#pragma unroll
        for (int c = 0; c < 32; c++) {
            int d = g + 16 * c;
            float ga = gamma[d], be = beta[d];
            out[base0 + d]       = (Oacc[c]      - mu0) * rstd0 * ga + be;
            out[base0 + DIM + d] = (Oacc[32 + c] - mu1) * rstd1 * ga + be;
        }
    }
}

// ---------------------------------------------------------------------------
// Launch
// ---------------------------------------------------------------------------
extern "C" void kernel_launch(void* const* d_in, const int* in_sizes, int n_in,
                              void* d_out, int out_size)
{
    const float* x0    = (const float*)d_in[0];
    const float* x1    = (const float*)d_in[1];
    const float* Wq    = (const float*)d_in[2];
    const float* Wk    = (const float*)d_in[3];
    const float* Wv    = (const float*)d_in[4];
    const float* gamma = (const float*)d_in[5];
    const float* beta  = (const float*)d_in[6];
    float* out = (float*)d_out;

    cudaFuncSetAttribute(qkv_hmma, cudaFuncAttributeMaxDynamicSharedMemorySize, GB_SMEM);
    const int attn_smem = (3 * 32 * ROW_STRIDE + 32 * 33 + 64) * (int)sizeof(float);
    cudaFuncSetAttribute(attn_kernel, cudaFuncAttributeMaxDynamicSharedMemorySize, attn_smem);

    conv_x<<<MTOT, 256>>>(x0, x1);
    conv_w<<<dim3(16, 32, 3), dim3(32, 8)>>>(Wq, Wk, Wv);
    qkv_hmma<<<dim3(12, 128), 256, GB_SMEM>>>();
    attn_kernel<<<dim3(SEQ / 32, BATCH), 256, attn_smem>>>(gamma, beta, out);
}

// round 5
// speedup vs baseline: 3.3793x; 2.3474x over previous
#include <cuda_runtime.h>
#include <cuda_bf16.h>
#include <math.h>

// Problem constants
#define BATCH 8
#define SEQ   2048
#define DIM   512
#define KDIM  1024
#define MTOT  (BATCH*SEQ)   // 16384

// Scratch (no cudaMalloc allowed)
__device__ __nv_bfloat16 g_Ah[(size_t)MTOT * KDIM];
__device__ __nv_bfloat16 g_Al[(size_t)MTOT * KDIM];
__device__ __nv_bfloat16 g_Wh[(size_t)3 * DIM * KDIM];
__device__ __nv_bfloat16 g_Wl[(size_t)3 * DIM * KDIM];
// q/k/v in bf16 hi/lo (written by GEMM epilogue)
__device__ __nv_bfloat16 g_qh[(size_t)MTOT * DIM];
__device__ __nv_bfloat16 g_ql[(size_t)MTOT * DIM];
__device__ __nv_bfloat16 g_kh[(size_t)MTOT * DIM];
__device__ __nv_bfloat16 g_kl[(size_t)MTOT * DIM];
__device__ __nv_bfloat16 g_vh[(size_t)MTOT * DIM];
__device__ __nv_bfloat16 g_vl[(size_t)MTOT * DIM];

// ---------------------------------------------------------------------------
// helpers
// ---------------------------------------------------------------------------
__device__ __forceinline__ unsigned smem_u32(const void* p) {
    unsigned a;
    asm("{ .reg .u64 t; cvta.to.shared.u64 t, %1; cvt.u32.u64 %0, t; }" : "=r"(a) : "l"(p));
    return a;
}
__device__ __forceinline__ void cpa16(unsigned dst, const void* src) {
    asm volatile("cp.async.cg.shared.global [%0], [%1], 16;"
                 :: "r"(dst), "l"(__cvta_generic_to_global(src)) : "memory");
}
__device__ __forceinline__ void cp_commit() {
    asm volatile("cp.async.commit_group;" ::: "memory");
}
template <int N>
__device__ __forceinline__ void cp_wait() {
    asm volatile("cp.async.wait_group %0;" :: "n"(N) : "memory");
}
__device__ __forceinline__ void ldsm4(unsigned* r, unsigned addr) {
    asm volatile("ldmatrix.sync.aligned.m8n8.x4.shared.b16 {%0,%1,%2,%3}, [%4];"
                 : "=r"(r[0]), "=r"(r[1]), "=r"(r[2]), "=r"(r[3]) : "r"(addr));
}
__device__ __forceinline__ void ldsm2(unsigned* r, unsigned addr) {
    asm volatile("ldmatrix.sync.aligned.m8n8.x2.shared.b16 {%0,%1}, [%2];"
                 : "=r"(r[0]), "=r"(r[1]) : "r"(addr));
}
__device__ __forceinline__ void ldsm4t(unsigned* r, unsigned addr) {
    asm volatile("ldmatrix.sync.aligned.m8n8.x4.trans.shared.b16 {%0,%1,%2,%3}, [%4];"
                 : "=r"(r[0]), "=r"(r[1]), "=r"(r[2]), "=r"(r[3]) : "r"(addr));
}
__device__ __forceinline__ void mma_bf16(float* c, const unsigned* a,
                                         unsigned b0, unsigned b1) {
    asm volatile(
        "mma.sync.aligned.m16n8k16.row.col.f32.bf16.bf16.f32 "
        "{%0,%1,%2,%3}, {%4,%5,%6,%7}, {%8,%9}, {%0,%1,%2,%3};"
        : "+f"(c[0]), "+f"(c[1]), "+f"(c[2]), "+f"(c[3])
        : "r"(a[0]), "r"(a[1]), "r"(a[2]), "r"(a[3]), "r"(b0), "r"(b1));
}

// ---------------------------------------------------------------------------
// Conversion: x0|x1 -> bf16 hi/lo, row-major [MTOT][1024]
// ---------------------------------------------------------------------------
__global__ __launch_bounds__(256)
void conv_x(const float* __restrict__ x0, const float* __restrict__ x1)
{
    unsigned t = blockIdx.x * 256u + threadIdx.x;
    unsigned m  = t >> 8;
    unsigned k4 = (t & 255u) * 4u;
    float4 v = (k4 < 512u)
        ? *(const float4*)(x0 + (size_t)m * 512 + k4)
        : *(const float4*)(x1 + (size_t)m * 512 + (k4 - 512u));
    __nv_bfloat16 h0 = __float2bfloat16(v.x);
    __nv_bfloat16 h1 = __float2bfloat16(v.y);
    __nv_bfloat16 h2 = __float2bfloat16(v.z);
    __nv_bfloat16 h3 = __float2bfloat16(v.w);
    __nv_bfloat16 l0 = __float2bfloat16(v.x - __bfloat162float(h0));
    __nv_bfloat16 l1 = __float2bfloat16(v.y - __bfloat162float(h1));
    __nv_bfloat16 l2 = __float2bfloat16(v.z - __bfloat162float(h2));
    __nv_bfloat16 l3 = __float2bfloat16(v.w - __bfloat162float(h3));
    size_t o = (size_t)m * 1024 + k4;
    __nv_bfloat162* dh = (__nv_bfloat162*)(g_Ah + o);
    __nv_bfloat162* dl = (__nv_bfloat162*)(g_Al + o);
    dh[0] = __nv_bfloat162(h0, h1); dh[1] = __nv_bfloat162(h2, h3);
    dl[0] = __nv_bfloat162(l0, l1); dl[1] = __nv_bfloat162(l2, l3);
}

// ---------------------------------------------------------------------------
// W[k][n] -> W^T hi/lo bf16, n-major rows (q scaled by 1/sqrt(D))
// ---------------------------------------------------------------------------
__global__ __launch_bounds__(256)
void conv_w(const float* __restrict__ Wq, const float* __restrict__ Wk,
            const float* __restrict__ Wv)
{
    __shared__ float tile[32][33];
    const int z  = blockIdx.z;
    const float* __restrict__ W = (z == 0) ? Wq : ((z == 1) ? Wk : Wv);
    const int n0 = blockIdx.x * 32;
    const int k0 = blockIdx.y * 32;
    const int tx = threadIdx.x;
    const int ty = threadIdx.y;

    for (int r = ty; r < 32; r += 8)
        tile[r][tx] = W[(size_t)(k0 + r) * 512 + n0 + tx];
    __syncthreads();

    const float scale = (z == 0) ? 0.04419417382415922f : 1.0f;
    for (int r = ty; r < 32; r += 8) {
        int n = n0 + r;
        int k = k0 + tx;
        float v = tile[tx][r] * scale;
        __nv_bfloat16 hi = __float2bfloat16(v);
        __nv_bfloat16 lo = __float2bfloat16(v - __bfloat162float(hi));
        size_t idx = ((size_t)(z * 512 + n)) * 1024 + k;
        g_Wh[idx] = hi;
        g_Wl[idx] = lo;
    }
}

// ---------------------------------------------------------------------------
// QKV GEMM via mma.sync bf16 split-2. Epilogue stores bf16 hi/lo q/k/v.
// ---------------------------------------------------------------------------
#define GB_BUF 40960
#define GB_SMEM (2 * GB_BUF)

__device__ __forceinline__ void gemm_issue(unsigned sb, int buf, int m0, int nbase,
                                           int k0, int tid)
{
    const int lr  = tid >> 1;
    const int lc0 = (tid & 1) * 2;
    unsigned base = sb + buf * GB_BUF;
    const __nv_bfloat16* pa_h = g_Ah + (size_t)(m0 + lr) * 1024 + k0;
    const __nv_bfloat16* pa_l = g_Al + (size_t)(m0 + lr) * 1024 + k0;
    const __nv_bfloat16* pb_h = g_Wh + (size_t)(nbase + lr) * 1024 + k0;
    const __nv_bfloat16* pb_l = g_Wl + (size_t)(nbase + lr) * 1024 + k0;
#pragma unroll
    for (int cc = 0; cc < 2; cc++) {
        int c = lc0 + cc;
        unsigned o = lr * 80 + c * 16;
        cpa16(base + o,          pa_h + c * 8);
        cpa16(base + 10240 + o,  pa_l + c * 8);
        cpa16(base + 20480 + o,  pb_h + c * 8);
        cpa16(base + 30720 + o,  pb_l + c * 8);
    }
    cp_commit();
}

__global__ __launch_bounds__(256, 2)
void qkv_hmma()
{
    extern __shared__ char smem[];
    unsigned sb = smem_u32(smem);
    const int tid  = threadIdx.x;
    const int lane = tid & 31;
    const int w    = tid >> 5;
    const int wm   = w >> 2;
    const int wn   = w & 3;
    const int nbase = blockIdx.x * 128;
    const int m0    = blockIdx.y * 128;

    float acc[4][4][4];
#pragma unroll
    for (int i = 0; i < 4; i++)
#pragma unroll
        for (int j = 0; j < 4; j++)
#pragma unroll
            for (int k = 0; k < 4; k++) acc[i][j][k] = 0.0f;

    const int mrowA = (lane & 7) + ((lane >> 3) & 1) * 8;
    const int kcA   = (lane >> 4) & 1;
    const int nrowB = (lane & 7) + ((lane >> 4) & 1) * 8;
    const int kcB   = (lane >> 3) & 1;
    const unsigned aoff = (wm * 64 + mrowA) * 80 + kcA * 16;
    const unsigned boff = 20480u + (wn * 32 + nrowB) * 80 + kcB * 16;

    gemm_issue(sb, 0, m0, nbase, 0, tid);

    for (int ch = 0; ch < 32; ++ch) {
        if (ch + 1 < 32) {
            gemm_issue(sb, (ch + 1) & 1, m0, nbase, (ch + 1) * 32, tid);
            cp_wait<1>();
        } else {
            cp_wait<0>();
        }
        __syncthreads();

        unsigned base = sb + (ch & 1) * GB_BUF;
#pragma unroll
        for (int ks = 0; ks < 2; ks++) {
            unsigned Bh[8], Bl[8];
            ldsm4(&Bh[0], base + boff + ks * 32);
            ldsm4(&Bh[4], base + boff + 16 * 80 + ks * 32);
            ldsm4(&Bl[0], base + boff + 10240 + ks * 32);
            ldsm4(&Bl[4], base + boff + 10240 + 16 * 80 + ks * 32);
#pragma unroll
            for (int mt = 0; mt < 4; mt++) {
                unsigned Ah[4], Al[4];
                ldsm4(Ah, base + aoff + mt * (16 * 80) + ks * 32);
                ldsm4(Al, base + aoff + 10240 + mt * (16 * 80) + ks * 32);
#pragma unroll
                for (int nt = 0; nt < 4; nt++) {
                    mma_bf16(acc[mt][nt], Ah, Bh[nt * 2], Bh[nt * 2 + 1]);
                    mma_bf16(acc[mt][nt], Ah, Bl[nt * 2], Bl[nt * 2 + 1]);
                    mma_bf16(acc[mt][nt], Al, Bh[nt * 2], Bh[nt * 2 + 1]);
                }
            }
        }
        __syncthreads();
    }

    // Epilogue: fp32 acc -> bf16 hi/lo stores
    const int z = nbase >> 9;
    __nv_bfloat16* Xh = (z == 0) ? g_qh : ((z == 1) ? g_kh : g_vh);
    __nv_bfloat16* Xl = (z == 0) ? g_ql : ((z == 1) ? g_kl : g_vl);
    const int colb = (nbase & 511) + wn * 32;
    const int gid = lane >> 2, tig = lane & 3;
#pragma unroll
    for (int mt = 0; mt < 4; mt++) {
#pragma unroll
        for (int nt = 0; nt < 4; nt++) {
            int row = m0 + wm * 64 + mt * 16 + gid;
            int col = colb + nt * 8 + tig * 2;
#pragma unroll
            for (int rr = 0; rr < 2; rr++) {
                float v0 = acc[mt][nt][rr * 2 + 0];
                float v1 = acc[mt][nt][rr * 2 + 1];
                __nv_bfloat16 h0 = __float2bfloat16(v0);
                __nv_bfloat16 h1 = __float2bfloat16(v1);
                __nv_bfloat16 l0 = __float2bfloat16(v0 - __bfloat162float(h0));
                __nv_bfloat16 l1 = __float2bfloat16(v1 - __bfloat162float(h1));
                size_t o = (size_t)(row + rr * 8) * 512 + col;
                *(__nv_bfloat162*)(Xh + o) = __nv_bfloat162(h0, h1);
                *(__nv_bfloat162*)(Xl + o) = __nv_bfloat162(l0, l1);
            }
        }
    }
}

// ---------------------------------------------------------------------------
// Tensor-core flash attention + fused LayerNorm.
// CTA = (b, 32-row q-tile), 256 threads (8 warps).
// S phase:  warp = (row-half rh) x (8-s-col group cg); split-3 bf16 mma over
//           4 d-chunks of 128 (K double-buffered cp.async).
// softmax:  SIMT, P -> bf16 hi/lo in smem.
// PV phase: warp = (row-half) x (128-d chunk); V^T via ldmatrix.trans; split-3.
// S pitch is 34 fp32 (even) so float2 fragment stores stay 8B-aligned.
// ---------------------------------------------------------------------------
#define PP 40       // P row pitch (bf16 elems) = 80B (odd*16B)
#define SD 34       // S row pitch (fp32) — even => float2-aligned

#define OQH 0
#define OQL 33280
#define OVH 66560
#define OVL 99840
#define OKH 133120              /* 2 bufs x 8704 */
#define OKL 150528
#define OS  167936              /* fp32 32x34 = 4352B */
#define OPH 172288
#define OPL 174848
#define OAL 177408              /* fp32 32 */
#define OLL 177536              /* fp32 32 */
#define ORS 177664              /* fp32 32x4 row-sum partials */
#define ORQ 178176              /* fp32 32x4 row-sumsq partials */
#define ATTN_SMEM 178688

#define NEG_INF __int_as_float(0xff800000)

__device__ __forceinline__ void attn_load_kv(unsigned sb, int buf, int dc,
                                             size_t srow0, int tid)
{
#pragma unroll
    for (int i = 0; i < 8; i++) {
        int idx = tid + i * 256;          // 0..2047
        int which = idx >> 9;             // 0:Kh 1:Kl 2:Vh 3:Vl
        int u = idx & 511;
        int row = u >> 4;                 // 0..31
        int c = u & 15;                   // 16B unit within 128 d
        const __nv_bfloat16* src;
        unsigned dst;
        if (which == 0) {
            src = g_kh + (srow0 + row) * 512 + dc * 128 + c * 8;
            dst = sb + OKH + buf * 8704 + row * 272 + c * 16;
        } else if (which == 1) {
            src = g_kl + (srow0 + row) * 512 + dc * 128 + c * 8;
            dst = sb + OKL + buf * 8704 + row * 272 + c * 16;
        } else if (which == 2) {
            src = g_vh + (srow0 + row) * 512 + dc * 128 + c * 8;
            dst = sb + OVH + row * 1040 + dc * 256 + c * 16;
        } else {
            src = g_vl + (srow0 + row) * 512 + dc * 128 + c * 8;
            dst = sb + OVL + row * 1040 + dc * 256 + c * 16;
        }
        cpa16(dst, src);
    }
    cp_commit();
}

__global__ __launch_bounds__(256, 1)
void attn_mma(const float* __restrict__ gamma, const float* __restrict__ beta,
              float* __restrict__ out)
{
    extern __shared__ char smc[];
    unsigned sb = smem_u32(smc);
    float* S    = (float*)(smc + OS);
    float* AL   = (float*)(smc + OAL);
    float* LL   = (float*)(smc + OLL);
    float* RS   = (float*)(smc + ORS);
    float* RQ   = (float*)(smc + ORQ);
    __nv_bfloat16* PH = (__nv_bfloat16*)(smc + OPH);
    __nv_bfloat16* PL = (__nv_bfloat16*)(smc + OPL);

    const int b   = blockIdx.y;
    const int qb  = gridDim.x - 1 - blockIdx.x;     // heavy tiles first
    const int tid = threadIdx.x;
    const int lane = tid & 31;
    const int w    = tid >> 5;
    const int rh   = w >> 2;       // S row-half / PV row-half
    const int cg   = w & 3;        // S col-group (8 s-cols)
    const int dcw  = w & 3;        // PV d-chunk (128 cols)
    const int ti = tid >> 4;       // softmax mapping
    const int tj = tid & 15;

    const size_t qrow0 = (size_t)b * SEQ + (size_t)qb * 32;

    // --- load Q (hi/lo) into smem ---
#pragma unroll
    for (int i = 0; i < 16; i++) {
        int idx = tid + i * 256;          // 0..4095
        int which = idx >> 11;            // 0:Qh 1:Ql
        int u = idx & 2047;
        int row = u >> 6;                 // 0..31
        int c = u & 63;                   // 16B unit of 512 elems
        const __nv_bfloat16* src = (which ? g_ql : g_qh) + (qrow0 + row) * 512 + c * 8;
        unsigned dst = sb + (which ? OQL : OQH) + row * 1040 + c * 16;
        cpa16(dst, src);
    }
    cp_commit();

    // PV accumulator: warp (rh, dcw): 16 rows x 128 cols -> 16 n-tiles x 4 regs
    float acc[16][4];
#pragma unroll
    for (int nt = 0; nt < 16; nt++)
#pragma unroll
        for (int k = 0; k < 4; k++) acc[nt][k] = 0.0f;

    // online softmax state (softmax mapping threads; rows 2ti, 2ti+1)
    float m0r = NEG_INF, m1r = NEG_INF;
    float l0r = 0.0f,    l1r = 0.0f;

    // ldmatrix address components
    const unsigned qrow_a = rh * 16 + (lane & 7) + ((lane >> 3) & 1) * 8;
    const unsigned kca    = ((lane >> 4) & 1) * 8;
    const unsigned krow_b = cg * 8 + (lane & 7);
    const unsigned kcb    = ((lane >> 3) & 1) * 8;
    // PV: P A-frag rows; V trans-B rows
    const unsigned prow_a = rh * 16 + (lane & 7) + ((lane >> 3) & 1) * 8;
    const unsigned vsrow  = ((lane >> 3) & 1) * 8 + (lane & 7);
    const unsigned vdoff  = ((lane >> 4) & 1) * 8;

    for (int jb = 0; jb <= qb; jb++) {
        const size_t srow0 = (size_t)b * SEQ + (size_t)jb * 32;

        attn_load_kv(sb, 0, 0, srow0, tid);   // g0
        attn_load_kv(sb, 1, 1, srow0, tid);   // g1

        // ---- S phase ----
        float sacc[4] = {0.f, 0.f, 0.f, 0.f};
#pragma unroll
        for (int dc = 0; dc < 4; dc++) {
            if (dc < 3) cp_wait<1>(); else cp_wait<0>();
            __syncthreads();
            unsigned kb = sb + (dc & 1) * 8704;
#pragma unroll
            for (int ks = 0; ks < 8; ks++) {
                unsigned qcol = (dc * 128 + ks * 16 + kca) * 2;
                unsigned Ah[4], Alo[4], Bh[2], Bl[2];
                ldsm4(Ah,  sb + OQH + qrow_a * 1040 + qcol);
                ldsm4(Alo, sb + OQL + qrow_a * 1040 + qcol);
                unsigned kcol = (ks * 16 + kcb) * 2;
                ldsm2(Bh, kb + OKH + krow_b * 272 + kcol);
                ldsm2(Bl, kb + OKL + krow_b * 272 + kcol);
                mma_bf16(sacc, Ah,  Bh[0], Bh[1]);
                mma_bf16(sacc, Alo, Bh[0], Bh[1]);
                mma_bf16(sacc, Ah,  Bl[0], Bl[1]);
            }
            __syncthreads();
            if (dc < 2) attn_load_kv(sb, dc & 1, dc + 2, srow0, tid);
        }

        // write S fragments to smem (pitch SD=34 keeps float2 8B-aligned)
        {
            int r  = lane >> 2;
            int c2 = (lane & 3) * 2;
            int row0 = rh * 16 + r;
            int col  = cg * 8 + c2;
            *(float2*)&S[row0 * SD + col]       = make_float2(sacc[0], sacc[1]);
            *(float2*)&S[(row0 + 8) * SD + col] = make_float2(sacc[2], sacc[3]);
        }
        __syncthreads();

        // ---- softmax (SIMT, 2x2 per thread) ----
        {
            float s00 = S[(2 * ti) * SD + 2 * tj];
            float s01 = S[(2 * ti) * SD + 2 * tj + 1];
            float s10 = S[(2 * ti + 1) * SD + 2 * tj];
            float s11 = S[(2 * ti + 1) * SD + 2 * tj + 1];

            if (jb == qb) {
                int qi0 = qb * 32 + 2 * ti;
                int kj0 = jb * 32 + 2 * tj;
                if (kj0     > qi0)     s00 = NEG_INF;
                if (kj0 + 1 > qi0)     s01 = NEG_INF;
                if (kj0     > qi0 + 1) s10 = NEG_INF;
                if (kj0 + 1 > qi0 + 1) s11 = NEG_INF;
            }

            float r0 = fmaxf(s00, s01);
            float r1 = fmaxf(s10, s11);
#pragma unroll
            for (int off = 1; off < 16; off <<= 1) {
                r0 = fmaxf(r0, __shfl_xor_sync(0xffffffffu, r0, off));
                r1 = fmaxf(r1, __shfl_xor_sync(0xffffffffu, r1, off));
            }
            float mn0 = fmaxf(m0r, r0);
            float mn1 = fmaxf(m1r, r1);
            float al0 = __expf(m0r - mn0);
            float al1 = __expf(m1r - mn1);

            float p00 = __expf(s00 - mn0), p01 = __expf(s01 - mn0);
            float p10 = __expf(s10 - mn1), p11 = __expf(s11 - mn1);

            float rs0 = p00 + p01;
            float rs1 = p10 + p11;
#pragma unroll
            for (int off = 1; off < 16; off <<= 1) {
                rs0 += __shfl_xor_sync(0xffffffffu, rs0, off);
                rs1 += __shfl_xor_sync(0xffffffffu, rs1, off);
            }
            l0r = al0 * l0r + rs0;  m0r = mn0;
            l1r = al1 * l1r + rs1;  m1r = mn1;

            if (tj == 0) {
                AL[2 * ti]     = al0;
                AL[2 * ti + 1] = al1;
                LL[2 * ti]     = l0r;
                LL[2 * ti + 1] = l1r;
            }
            __nv_bfloat16 h00 = __float2bfloat16(p00);
            __nv_bfloat16 h01 = __float2bfloat16(p01);
            __nv_bfloat16 h10 = __float2bfloat16(p10);
            __nv_bfloat16 h11 = __float2bfloat16(p11);
            *(__nv_bfloat162*)&PH[(2 * ti) * PP + 2 * tj]     = __nv_bfloat162(h00, h01);
            *(__nv_bfloat162*)&PH[(2 * ti + 1) * PP + 2 * tj] = __nv_bfloat162(h10, h11);
            *(__nv_bfloat162*)&PL[(2 * ti) * PP + 2 * tj] = __nv_bfloat162(
                __float2bfloat16(p00 - __bfloat162float(h00)),
                __float2bfloat16(p01 - __bfloat162float(h01)));
            *(__nv_bfloat162*)&PL[(2 * ti + 1) * PP + 2 * tj] = __nv_bfloat162(
                __float2bfloat16(p10 - __bfloat162float(h10)),
                __float2bfloat16(p11 - __bfloat162float(h11)));
        }
        __syncthreads();

        // ---- PV phase: warp (rh, dcw) ----
        {
            float a0 = AL[rh * 16 + (lane >> 2)];
            float a1 = AL[rh * 16 + (lane >> 2) + 8];
#pragma unroll
            for (int nt = 0; nt < 16; nt++) {
                acc[nt][0] *= a0; acc[nt][1] *= a0;
                acc[nt][2] *= a1; acc[nt][3] *= a1;
            }
#pragma unroll
            for (int ks2 = 0; ks2 < 2; ks2++) {
                unsigned Ph[4], Pl[4];
                unsigned pcol = (ks2 * 16 + ((lane >> 4) & 1) * 8) * 2;
                ldsm4(Ph, sb + OPH + prow_a * 80 + pcol);
                ldsm4(Pl, sb + OPL + prow_a * 80 + pcol);
                unsigned vrow = (ks2 * 16 + vsrow) * 1040;
#pragma unroll
                for (int ng = 0; ng < 8; ng++) {
                    unsigned vcol = (dcw * 128 + ng * 16 + vdoff) * 2;
                    unsigned Bh[4], Bl[4];
                    ldsm4t(Bh, sb + OVH + vrow + vcol);
                    ldsm4t(Bl, sb + OVL + vrow + vcol);
                    mma_bf16(acc[ng * 2],     Ph, Bh[0], Bh[1]);
                    mma_bf16(acc[ng * 2],     Pl, Bh[0], Bh[1]);
                    mma_bf16(acc[ng * 2],     Ph, Bl[0], Bl[1]);
                    mma_bf16(acc[ng * 2 + 1], Ph, Bh[2], Bh[3]);
                    mma_bf16(acc[ng * 2 + 1], Pl, Bh[2], Bh[3]);
                    mma_bf16(acc[ng * 2 + 1], Ph, Bl[2], Bl[3]);
                }
            }
        }
        __syncthreads();   // protect V/K smem before next iter's cp.async
    }

    // ---- epilogue: 1/l, LayerNorm, store ----
    {
        int r  = lane >> 2;
        int c2 = (lane & 3) * 2;
        int row0 = rh * 16 + r;
        int row1 = row0 + 8;
        float linv0 = 1.0f / LL[row0];
        float linv1 = 1.0f / LL[row1];
        float s0 = 0.f, q0 = 0.f, s1 = 0.f, q1 = 0.f;
#pragma unroll
        for (int nt = 0; nt < 16; nt++) {
            acc[nt][0] *= linv0; acc[nt][1] *= linv0;
            acc[nt][2] *= linv1; acc[nt][3] *= linv1;
            s0 += acc[nt][0] + acc[nt][1];
            q0 += acc[nt][0] * acc[nt][0] + acc[nt][1] * acc[nt][1];
            s1 += acc[nt][2] + acc[nt][3];
            q1 += acc[nt][2] * acc[nt][2] + acc[nt][3] * acc[nt][3];
        }
#pragma unroll
        for (int off = 1; off < 4; off <<= 1) {
            s0 += __shfl_xor_sync(0xffffffffu, s0, off);
            q0 += __shfl_xor_sync(0xffffffffu, q0, off);
            s1 += __shfl_xor_sync(0xffffffffu, s1, off);
            q1 += __shfl_xor_sync(0xffffffffu, q1, off);
        }
        if ((lane & 3) == 0) {
            RS[row0 * 4 + dcw] = s0;  RQ[row0 * 4 + dcw] = q0;
            RS[row1 * 4 + dcw] = s1;  RQ[row1 * 4 + dcw] = q1;
        }
        __syncthreads();
        float ts0 = RS[row0 * 4] + RS[row0 * 4 + 1] + RS[row0 * 4 + 2] + RS[row0 * 4 + 3];
        float tq0 = RQ[row0 * 4] + RQ[row0 * 4 + 1] + RQ[row0 * 4 + 2] + RQ[row0 * 4 + 3];
        float ts1 = RS[row1 * 4] + RS[row1 * 4 + 1] + RS[row1 * 4 + 2] + RS[row1 * 4 + 3];
        float tq1 = RQ[row1 * 4] + RQ[row1 * 4 + 1] + RQ[row1 * 4 + 2] + RQ[row1 * 4 + 3];
        const float invD = 1.0f / (float)DIM;
        float mu0 = ts0 * invD, var0 = tq0 * invD - mu0 * mu0;
        float mu1 = ts1 * invD, var1 = tq1 * invD - mu1 * mu1;
        float rstd0 = rsqrtf(var0 + 1e-5f);
        float rstd1 = rsqrtf(var1 + 1e-5f);

        size_t ob0 = (qrow0 + row0) * 512;
        size_t ob1 = (qrow0 + row1) * 512;
#pragma unroll
        for (int nt = 0; nt < 16; nt++) {
            int col = dcw * 128 + nt * 8 + c2;
            float g0 = gamma[col], g1 = gamma[col + 1];
            float be0 = beta[col], be1 = beta[col + 1];
            float2 o0 = make_float2((acc[nt][0] - mu0) * rstd0 * g0 + be0,
                                    (acc[nt][1] - mu0) * rstd0 * g1 + be1);
            float2 o1 = make_float2((acc[nt][2] - mu1) * rstd1 * g0 + be0,
                                    (acc[nt][3] - mu1) * rstd1 * g1 + be1);
            *(float2*)(out + ob0 + col) = o0;
            *(float2*)(out + ob1 + col) = o1;
        }
    }
}

// ---------------------------------------------------------------------------
// Launch
// ---------------------------------------------------------------------------
extern "C" void kernel_launch(void* const* d_in, const int* in_sizes, int n_in,
                              void* d_out, int out_size)
{
    const float* x0    = (const float*)d_in[0];
    const float* x1    = (const float*)d_in[1];
    const float* Wq    = (const float*)d_in[2];
    const float* Wk    = (const float*)d_in[3];
    const float* Wv    = (const float*)d_in[4];
    const float* gamma = (const float*)d_in[5];
    const float* beta  = (const float*)d_in[6];
    float* out = (float*)d_out;

    cudaFuncSetAttribute(qkv_hmma, cudaFuncAttributeMaxDynamicSharedMemorySize, GB_SMEM);
    cudaFuncSetAttribute(attn_mma, cudaFuncAttributeMaxDynamicSharedMemorySize, ATTN_SMEM);

    conv_x<<<MTOT, 256>>>(x0, x1);
    conv_w<<<dim3(16, 32, 3), dim3(32, 8)>>>(Wq, Wk, Wv);
    qkv_hmma<<<dim3(12, 128), 256, GB_SMEM>>>();
    attn_mma<<<dim3(SEQ / 32, BATCH), 256, ATTN_SMEM>>>(gamma, beta, out);
}

// round 6
// speedup vs baseline: 3.5518x; 1.0511x over previous
#include <cuda_runtime.h>
#include <cuda_bf16.h>
#include <math.h>

// Problem constants
#define BATCH 8
#define SEQ   2048
#define DIM   512
#define KDIM  1024
#define MTOT  (BATCH*SEQ)   // 16384

// Scratch (no cudaMalloc allowed)
__device__ __nv_bfloat16 g_Ah[(size_t)MTOT * KDIM];
__device__ __nv_bfloat16 g_Al[(size_t)MTOT * KDIM];
__device__ __nv_bfloat16 g_Wh[(size_t)3 * DIM * KDIM];
__device__ __nv_bfloat16 g_Wl[(size_t)3 * DIM * KDIM];
__device__ __nv_bfloat16 g_qh[(size_t)MTOT * DIM];
__device__ __nv_bfloat16 g_ql[(size_t)MTOT * DIM];
__device__ __nv_bfloat16 g_kh[(size_t)MTOT * DIM];
__device__ __nv_bfloat16 g_kl[(size_t)MTOT * DIM];
__device__ __nv_bfloat16 g_vh[(size_t)MTOT * DIM];
__device__ __nv_bfloat16 g_vl[(size_t)MTOT * DIM];

// ---------------------------------------------------------------------------
// helpers
// ---------------------------------------------------------------------------
__device__ __forceinline__ unsigned smem_u32(const void* p) {
    unsigned a;
    asm("{ .reg .u64 t; cvta.to.shared.u64 t, %1; cvt.u32.u64 %0, t; }" : "=r"(a) : "l"(p));
    return a;
}
__device__ __forceinline__ void cpa16(unsigned dst, const void* src) {
    asm volatile("cp.async.cg.shared.global [%0], [%1], 16;"
                 :: "r"(dst), "l"(__cvta_generic_to_global(src)) : "memory");
}
__device__ __forceinline__ void cp_commit() {
    asm volatile("cp.async.commit_group;" ::: "memory");
}
template <int N>
__device__ __forceinline__ void cp_wait() {
    asm volatile("cp.async.wait_group %0;" :: "n"(N) : "memory");
}
__device__ __forceinline__ void ldsm4(unsigned* r, unsigned addr) {
    asm volatile("ldmatrix.sync.aligned.m8n8.x4.shared.b16 {%0,%1,%2,%3}, [%4];"
                 : "=r"(r[0]), "=r"(r[1]), "=r"(r[2]), "=r"(r[3]) : "r"(addr));
}
__device__ __forceinline__ void ldsm2(unsigned* r, unsigned addr) {
    asm volatile("ldmatrix.sync.aligned.m8n8.x2.shared.b16 {%0,%1}, [%2];"
                 : "=r"(r[0]), "=r"(r[1]) : "r"(addr));
}
__device__ __forceinline__ void ldsm4t(unsigned* r, unsigned addr) {
    asm volatile("ldmatrix.sync.aligned.m8n8.x4.trans.shared.b16 {%0,%1,%2,%3}, [%4];"
                 : "=r"(r[0]), "=r"(r[1]), "=r"(r[2]), "=r"(r[3]) : "r"(addr));
}
__device__ __forceinline__ void mma_bf16(float* c, const unsigned* a,
                                         unsigned b0, unsigned b1) {
    asm volatile(
        "mma.sync.aligned.m16n8k16.row.col.f32.bf16.bf16.f32 "
        "{%0,%1,%2,%3}, {%4,%5,%6,%7}, {%8,%9}, {%0,%1,%2,%3};"
        : "+f"(c[0]), "+f"(c[1]), "+f"(c[2]), "+f"(c[3])
        : "r"(a[0]), "r"(a[1]), "r"(a[2]), "r"(a[3]), "r"(b0), "r"(b1));
}

// ---------------------------------------------------------------------------
// Conversion: x0|x1 -> bf16 hi/lo, row-major [MTOT][1024]
// ---------------------------------------------------------------------------
__global__ __launch_bounds__(256)
void conv_x(const float* __restrict__ x0, const float* __restrict__ x1)
{
    unsigned t = blockIdx.x * 256u + threadIdx.x;
    unsigned m  = t >> 8;
    unsigned k4 = (t & 255u) * 4u;
    float4 v = (k4 < 512u)
        ? *(const float4*)(x0 + (size_t)m * 512 + k4)
        : *(const float4*)(x1 + (size_t)m * 512 + (k4 - 512u));
    __nv_bfloat16 h0 = __float2bfloat16(v.x);
    __nv_bfloat16 h1 = __float2bfloat16(v.y);
    __nv_bfloat16 h2 = __float2bfloat16(v.z);
    __nv_bfloat16 h3 = __float2bfloat16(v.w);
    __nv_bfloat16 l0 = __float2bfloat16(v.x - __bfloat162float(h0));
    __nv_bfloat16 l1 = __float2bfloat16(v.y - __bfloat162float(h1));
    __nv_bfloat16 l2 = __float2bfloat16(v.z - __bfloat162float(h2));
    __nv_bfloat16 l3 = __float2bfloat16(v.w - __bfloat162float(h3));
    size_t o = (size_t)m * 1024 + k4;
    __nv_bfloat162* dh = (__nv_bfloat162*)(g_Ah + o);
    __nv_bfloat162* dl = (__nv_bfloat162*)(g_Al + o);
    dh[0] = __nv_bfloat162(h0, h1); dh[1] = __nv_bfloat162(h2, h3);
    dl[0] = __nv_bfloat162(l0, l1); dl[1] = __nv_bfloat162(l2, l3);
}

// ---------------------------------------------------------------------------
// W[k][n] -> W^T hi/lo bf16, n-major rows (q scaled by 1/sqrt(D))
// ---------------------------------------------------------------------------
__global__ __launch_bounds__(256)
void conv_w(const float* __restrict__ Wq, const float* __restrict__ Wk,
            const float* __restrict__ Wv)
{
    __shared__ float tile[32][33];
    const int z  = blockIdx.z;
    const float* __restrict__ W = (z == 0) ? Wq : ((z == 1) ? Wk : Wv);
    const int n0 = blockIdx.x * 32;
    const int k0 = blockIdx.y * 32;
    const int tx = threadIdx.x;
    const int ty = threadIdx.y;

    for (int r = ty; r < 32; r += 8)
        tile[r][tx] = W[(size_t)(k0 + r) * 512 + n0 + tx];
    __syncthreads();

    const float scale = (z == 0) ? 0.04419417382415922f : 1.0f;
    for (int r = ty; r < 32; r += 8) {
        int n = n0 + r;
        int k = k0 + tx;
        float v = tile[tx][r] * scale;
        __nv_bfloat16 hi = __float2bfloat16(v);
        __nv_bfloat16 lo = __float2bfloat16(v - __bfloat162float(hi));
        size_t idx = ((size_t)(z * 512 + n)) * 1024 + k;
        g_Wh[idx] = hi;
        g_Wl[idx] = lo;
    }
}

// ---------------------------------------------------------------------------
// QKV GEMM via mma.sync bf16 split-2. Epilogue stores bf16 hi/lo q/k/v.
// ---------------------------------------------------------------------------
#define GB_BUF 40960
#define GB_SMEM (2 * GB_BUF)

__device__ __forceinline__ void gemm_issue(unsigned sb, int buf, int m0, int nbase,
                                           int k0, int tid)
{
    const int lr  = tid >> 1;
    const int lc0 = (tid & 1) * 2;
    unsigned base = sb + buf * GB_BUF;
    const __nv_bfloat16* pa_h = g_Ah + (size_t)(m0 + lr) * 1024 + k0;
    const __nv_bfloat16* pa_l = g_Al + (size_t)(m0 + lr) * 1024 + k0;
    const __nv_bfloat16* pb_h = g_Wh + (size_t)(nbase + lr) * 1024 + k0;
    const __nv_bfloat16* pb_l = g_Wl + (size_t)(nbase + lr) * 1024 + k0;
#pragma unroll
    for (int cc = 0; cc < 2; cc++) {
        int c = lc0 + cc;
        unsigned o = lr * 80 + c * 16;
        cpa16(base + o,          pa_h + c * 8);
        cpa16(base + 10240 + o,  pa_l + c * 8);
        cpa16(base + 20480 + o,  pb_h + c * 8);
        cpa16(base + 30720 + o,  pb_l + c * 8);
    }
    cp_commit();
}

__global__ __launch_bounds__(256, 2)
void qkv_hmma()
{
    extern __shared__ char smem[];
    unsigned sb = smem_u32(smem);
    const int tid  = threadIdx.x;
    const int lane = tid & 31;
    const int w    = tid >> 5;
    const int wm   = w >> 2;
    const int wn   = w & 3;
    const int nbase = blockIdx.x * 128;
    const int m0    = blockIdx.y * 128;

    float acc[4][4][4];
#pragma unroll
    for (int i = 0; i < 4; i++)
#pragma unroll
        for (int j = 0; j < 4; j++)
#pragma unroll
            for (int k = 0; k < 4; k++) acc[i][j][k] = 0.0f;

    const int mrowA = (lane & 7) + ((lane >> 3) & 1) * 8;
    const int kcA   = (lane >> 4) & 1;
    const int nrowB = (lane & 7) + ((lane >> 4) & 1) * 8;
    const int kcB   = (lane >> 3) & 1;
    const unsigned aoff = (wm * 64 + mrowA) * 80 + kcA * 16;
    const unsigned boff = 20480u + (wn * 32 + nrowB) * 80 + kcB * 16;

    gemm_issue(sb, 0, m0, nbase, 0, tid);

    for (int ch = 0; ch < 32; ++ch) {
        if (ch + 1 < 32) {
            gemm_issue(sb, (ch + 1) & 1, m0, nbase, (ch + 1) * 32, tid);
            cp_wait<1>();
        } else {
            cp_wait<0>();
        }
        __syncthreads();

        unsigned base = sb + (ch & 1) * GB_BUF;
#pragma unroll
        for (int ks = 0; ks < 2; ks++) {
            unsigned Bh[8], Bl[8];
            ldsm4(&Bh[0], base + boff + ks * 32);
            ldsm4(&Bh[4], base + boff + 16 * 80 + ks * 32);
            ldsm4(&Bl[0], base + boff + 10240 + ks * 32);
            ldsm4(&Bl[4], base + boff + 10240 + 16 * 80 + ks * 32);
#pragma unroll
            for (int mt = 0; mt < 4; mt++) {
                unsigned Ah[4], Al[4];
                ldsm4(Ah, base + aoff + mt * (16 * 80) + ks * 32);
                ldsm4(Al, base + aoff + 10240 + mt * (16 * 80) + ks * 32);
#pragma unroll
                for (int nt = 0; nt < 4; nt++) {
                    mma_bf16(acc[mt][nt], Ah, Bh[nt * 2], Bh[nt * 2 + 1]);
                    mma_bf16(acc[mt][nt], Ah, Bl[nt * 2], Bl[nt * 2 + 1]);
                    mma_bf16(acc[mt][nt], Al, Bh[nt * 2], Bh[nt * 2 + 1]);
                }
            }
        }
        __syncthreads();
    }

    // Epilogue: fp32 acc -> bf16 hi/lo stores
    const int z = nbase >> 9;
    __nv_bfloat16* Xh = (z == 0) ? g_qh : ((z == 1) ? g_kh : g_vh);
    __nv_bfloat16* Xl = (z == 0) ? g_ql : ((z == 1) ? g_kl : g_vl);
    const int colb = (nbase & 511) + wn * 32;
    const int gid = lane >> 2, tig = lane & 3;
#pragma unroll
    for (int mt = 0; mt < 4; mt++) {
#pragma unroll
        for (int nt = 0; nt < 4; nt++) {
            int row = m0 + wm * 64 + mt * 16 + gid;
            int col = colb + nt * 8 + tig * 2;
#pragma unroll
            for (int rr = 0; rr < 2; rr++) {
                float v0 = acc[mt][nt][rr * 2 + 0];
                float v1 = acc[mt][nt][rr * 2 + 1];
                __nv_bfloat16 h0 = __float2bfloat16(v0);
                __nv_bfloat16 h1 = __float2bfloat16(v1);
                __nv_bfloat16 l0 = __float2bfloat16(v0 - __bfloat162float(h0));
                __nv_bfloat16 l1 = __float2bfloat16(v1 - __bfloat162float(h1));
                size_t o = (size_t)(row + rr * 8) * 512 + col;
                *(__nv_bfloat162*)(Xh + o) = __nv_bfloat162(h0, h1);
                *(__nv_bfloat162*)(Xl + o) = __nv_bfloat162(l0, l1);
            }
        }
    }
}

// ---------------------------------------------------------------------------
// Tensor-core flash attention + fused LayerNorm.
// CTA = (b, 64-row q-tile), 512 threads (16 warps). KV tiles of 32 keys.
// K and V streamed in 128-d chunks through 4 rotating cp.async buffers.
// S phase:  4x4 warp grid (16 rows x 8 cols each); 3 independent split accs.
// softmax:  SIMT, 512 threads cover 64x32 (2x2 each).
// PV phase: 4x4 warp grid (rh x vg): 16 rows x 32 cols per 128-d chunk.
// ---------------------------------------------------------------------------
#define PP 40       // P row pitch (bf16) = 80B
#define SD 34       // S row pitch (fp32), even => float2-aligned

#define OQH 0                    /* 64 x 1040B */
#define OQL 66560
#define OCH 133120               /* 4 chunk bufs x 17408B (hi 8704 | lo 8704) */
#define OS  202752               /* fp32 64 x 34 */
#define OPH 211456               /* bf16 64 x 40 */
#define OPL 216576
#define OAL 221696               /* fp32 64 */
#define OLL 221952               /* fp32 64 */
#define ORS 222208               /* fp32 64 x 4 */
#define ORQ 223232               /* fp32 64 x 4 */
#define ATTN_SMEM 224256

#define NEG_INF __int_as_float(0xff800000)

// Load one 32-row x 128-col hi/lo chunk of K or V into rotating buffer `buf`.
__device__ __forceinline__ void attn_load_chunk(unsigned sb, int buf,
                                                const __nv_bfloat16* Xh,
                                                const __nv_bfloat16* Xl,
                                                size_t srow0, int dc, int tid)
{
#pragma unroll
    for (int i = 0; i < 2; i++) {
        int idx = tid + i * 512;          // 0..1023
        int which = idx >> 9;             // 0:hi 1:lo
        int u = idx & 511;
        int row = u >> 4;                 // 0..31
        int c = u & 15;
        const __nv_bfloat16* src = (which ? Xl : Xh) + (srow0 + row) * 512 + dc * 128 + c * 8;
        unsigned dst = sb + OCH + buf * 17408 + which * 8704 + row * 272 + c * 16;
        cpa16(dst, src);
    }
    cp_commit();
}

__global__ __launch_bounds__(512, 1)
void attn_mma(const float* __restrict__ gamma, const float* __restrict__ beta,
              float* __restrict__ out)
{
    extern __shared__ char smc[];
    unsigned sb = smem_u32(smc);
    float* S    = (float*)(smc + OS);
    float* AL   = (float*)(smc + OAL);
    float* LL   = (float*)(smc + OLL);
    float* RS   = (float*)(smc + ORS);
    float* RQ   = (float*)(smc + ORQ);
    __nv_bfloat16* PH = (__nv_bfloat16*)(smc + OPH);
    __nv_bfloat16* PL = (__nv_bfloat16*)(smc + OPL);

    const int b   = blockIdx.y;
    const int qb  = gridDim.x - 1 - blockIdx.x;     // heavy tiles first
    const int tid = threadIdx.x;
    const int lane = tid & 31;
    const int w    = tid >> 5;      // 0..15
    const int rh   = w >> 2;        // 0..3 (16-row group)
    const int cg   = w & 3;         // S col-group (8 cols)
    const int vg   = w & 3;         // PV col-group (32 cols within chunk)
    const int ti = tid >> 4;        // 0..31 -> rows 2ti, 2ti+1
    const int tj = tid & 15;

    const size_t qrow0 = (size_t)b * SEQ + (size_t)qb * 64;

    // --- load Q (64 x 512 hi/lo) ---
#pragma unroll
    for (int i = 0; i < 16; i++) {
        int idx = tid + i * 512;          // 0..8191
        int which = idx >> 12;            // 0:Qh 1:Ql
        int u = idx & 4095;
        int row = u >> 6;                 // 0..63
        int c = u & 63;
        const __nv_bfloat16* src = (which ? g_ql : g_qh) + (qrow0 + row) * 512 + c * 8;
        unsigned dst = sb + (which ? OQL : OQH) + row * 1040 + c * 16;
        cpa16(dst, src);
    }
    cp_commit();

    // PV accumulator: acc[dc][nt][4] — 16 rows x (dc*128 + vg*32 + nt*8) cols
    float acc[4][4][4];
#pragma unroll
    for (int d = 0; d < 4; d++)
#pragma unroll
        for (int nt = 0; nt < 4; nt++)
#pragma unroll
            for (int k = 0; k < 4; k++) acc[d][nt][k] = 0.0f;

    float m0r = NEG_INF, m1r = NEG_INF;
    float l0r = 0.0f,    l1r = 0.0f;

    // ldmatrix lane components
    const unsigned qrow_a = rh * 16 + (lane & 7) + ((lane >> 3) & 1) * 8;
    const unsigned kca    = ((lane >> 4) & 1) * 8;
    const unsigned krow_b = cg * 8 + (lane & 7);
    const unsigned kcb    = ((lane >> 3) & 1) * 8;
    const unsigned prow_a = rh * 16 + (lane & 7) + ((lane >> 3) & 1) * 8;
    const unsigned vsrow  = ((lane >> 3) & 1) * 8 + (lane & 7);
    const unsigned vdoff  = ((lane >> 4) & 1) * 8;

    const int jbmax = 2 * qb + 1;

    // prefetch K chunks 0,1 of jb=0
    attn_load_chunk(sb, 0, g_kh, g_kl, (size_t)b * SEQ, 0, tid);
    attn_load_chunk(sb, 1, g_kh, g_kl, (size_t)b * SEQ, 1, tid);

    for (int jb = 0; jb <= jbmax; jb++) {
        const size_t srow0 = (size_t)b * SEQ + (size_t)jb * 32;
        const bool last = (jb == jbmax);

        // ---- S phase ----
        float shh[4] = {0,0,0,0}, shl[4] = {0,0,0,0}, slh[4] = {0,0,0,0};
#pragma unroll
        for (int dc = 0; dc < 4; dc++) {
            cp_wait<1>();
            __syncthreads();
            unsigned kb = sb + OCH + dc * 17408;
#pragma unroll
            for (int ks = 0; ks < 8; ks++) {
                unsigned qcol = (dc * 128 + ks * 16 + kca) * 2;
                unsigned Ah[4], Alo[4], Bh[2], Bl[2];
                ldsm4(Ah,  sb + OQH + qrow_a * 1040 + qcol);
                ldsm4(Alo, sb + OQL + qrow_a * 1040 + qcol);
                unsigned kcol = (ks * 16 + kcb) * 2;
                ldsm2(Bh, kb + krow_b * 272 + kcol);
                ldsm2(Bl, kb + 8704 + krow_b * 272 + kcol);
                mma_bf16(shh, Ah,  Bh[0], Bh[1]);
                mma_bf16(slh, Alo, Bh[0], Bh[1]);
                mma_bf16(shl, Ah,  Bl[0], Bl[1]);
            }
            if (dc < 2)
                attn_load_chunk(sb, dc + 2, g_kh, g_kl, srow0, dc + 2, tid);
            else
                attn_load_chunk(sb, dc - 2, g_vh, g_vl, srow0, dc - 2, tid);
        }

        // write S fragments
        {
            int r  = lane >> 2;
            int c2 = (lane & 3) * 2;
            int row0 = rh * 16 + r;
            int col  = cg * 8 + c2;
            float2 v0 = make_float2(shh[0] + shl[0] + slh[0], shh[1] + shl[1] + slh[1]);
            float2 v1 = make_float2(shh[2] + shl[2] + slh[2], shh[3] + shl[3] + slh[3]);
            *(float2*)&S[row0 * SD + col]       = v0;
            *(float2*)&S[(row0 + 8) * SD + col] = v1;
        }
        __syncthreads();

        // ---- softmax (SIMT, 2x2 per thread; 512 threads cover 64x32) ----
        {
            float s00 = S[(2 * ti) * SD + 2 * tj];
            float s01 = S[(2 * ti) * SD + 2 * tj + 1];
            float s10 = S[(2 * ti + 1) * SD + 2 * tj];
            float s11 = S[(2 * ti + 1) * SD + 2 * tj + 1];

            if (jb >= 2 * qb) {
                int qi0 = qb * 64 + 2 * ti;
                int kj0 = jb * 32 + 2 * tj;
                if (kj0     > qi0)     s00 = NEG_INF;
                if (kj0 + 1 > qi0)     s01 = NEG_INF;
                if (kj0     > qi0 + 1) s10 = NEG_INF;
                if (kj0 + 1 > qi0 + 1) s11 = NEG_INF;
            }

            float r0 = fmaxf(s00, s01);
            float r1 = fmaxf(s10, s11);
#pragma unroll
            for (int off = 1; off < 16; off <<= 1) {
                r0 = fmaxf(r0, __shfl_xor_sync(0xffffffffu, r0, off));
                r1 = fmaxf(r1, __shfl_xor_sync(0xffffffffu, r1, off));
            }
            float mn0 = fmaxf(m0r, r0);
            float mn1 = fmaxf(m1r, r1);
            float al0 = __expf(m0r - mn0);
            float al1 = __expf(m1r - mn1);

            float p00 = __expf(s00 - mn0), p01 = __expf(s01 - mn0);
            float p10 = __expf(s10 - mn1), p11 = __expf(s11 - mn1);

            float rs0 = p00 + p01;
            float rs1 = p10 + p11;
#pragma unroll
            for (int off = 1; off < 16; off <<= 1) {
                rs0 += __shfl_xor_sync(0xffffffffu, rs0, off);
                rs1 += __shfl_xor_sync(0xffffffffu, rs1, off);
            }
            l0r = al0 * l0r + rs0;  m0r = mn0;
            l1r = al1 * l1r + rs1;  m1r = mn1;

            if (tj == 0) {
                AL[2 * ti]     = al0;
                AL[2 * ti + 1] = al1;
                LL[2 * ti]     = l0r;
                LL[2 * ti + 1] = l1r;
            }
            __nv_bfloat16 h00 = __float2bfloat16(p00);
            __nv_bfloat16 h01 = __float2bfloat16(p01);
            __nv_bfloat16 h10 = __float2bfloat16(p10);
            __nv_bfloat16 h11 = __float2bfloat16(p11);
            *(__nv_bfloat162*)&PH[(2 * ti) * PP + 2 * tj]     = __nv_bfloat162(h00, h01);
            *(__nv_bfloat162*)&PH[(2 * ti + 1) * PP + 2 * tj] = __nv_bfloat162(h10, h11);
            *(__nv_bfloat162*)&PL[(2 * ti) * PP + 2 * tj] = __nv_bfloat162(
                __float2bfloat16(p00 - __bfloat162float(h00)),
                __float2bfloat16(p01 - __bfloat162float(h01)));
            *(__nv_bfloat162*)&PL[(2 * ti + 1) * PP + 2 * tj] = __nv_bfloat162(
                __float2bfloat16(p10 - __bfloat162float(h10)),
                __float2bfloat16(p11 - __bfloat162float(h11)));
        }
        __syncthreads();

        // scale accumulators by alpha
        {
            float a0 = AL[rh * 16 + (lane >> 2)];
            float a1 = AL[rh * 16 + (lane >> 2) + 8];
#pragma unroll
            for (int d = 0; d < 4; d++)
#pragma unroll
                for (int nt = 0; nt < 4; nt++) {
                    acc[d][nt][0] *= a0; acc[d][nt][1] *= a0;
                    acc[d][nt][2] *= a1; acc[d][nt][3] *= a1;
                }
        }

        // ---- PV phase (streamed V chunks) ----
#pragma unroll
        for (int dc = 0; dc < 4; dc++) {
            if (last && dc == 3) cp_wait<0>(); else cp_wait<1>();
            __syncthreads();
            unsigned vb = sb + OCH + dc * 17408;
#pragma unroll
            for (int ks2 = 0; ks2 < 2; ks2++) {
                unsigned Ph[4], Pl[4];
                unsigned pcol = (ks2 * 16 + ((lane >> 4) & 1) * 8) * 2;
                ldsm4(Ph, sb + OPH + prow_a * 80 + pcol);
                ldsm4(Pl, sb + OPL + prow_a * 80 + pcol);
                unsigned vrow = (ks2 * 16 + vsrow) * 272;
#pragma unroll
                for (int ng2 = 0; ng2 < 2; ng2++) {
                    unsigned vcol = (vg * 32 + ng2 * 16 + vdoff) * 2;
                    unsigned Bh[4], Bl[4];
                    ldsm4t(Bh, vb + vrow + vcol);
                    ldsm4t(Bl, vb + 8704 + vrow + vcol);
                    int nt0 = ng2 * 2, nt1 = ng2 * 2 + 1;
                    mma_bf16(acc[dc][nt0], Ph, Bh[0], Bh[1]);
                    mma_bf16(acc[dc][nt0], Pl, Bh[0], Bh[1]);
                    mma_bf16(acc[dc][nt0], Ph, Bl[0], Bl[1]);
                    mma_bf16(acc[dc][nt1], Ph, Bh[2], Bh[3]);
                    mma_bf16(acc[dc][nt1], Pl, Bh[2], Bh[3]);
                    mma_bf16(acc[dc][nt1], Ph, Bl[2], Bl[3]);
                }
            }
            if (dc < 2)
                attn_load_chunk(sb, dc + 2, g_vh, g_vl, srow0, dc + 2, tid);
            else if (!last)
                attn_load_chunk(sb, dc - 2, g_kh, g_kl, srow0 + 32, dc - 2, tid);
        }
    }

    // ---- epilogue: 1/l, LayerNorm, store ----
    {
        int r  = lane >> 2;
        int c2 = (lane & 3) * 2;
        int row0 = rh * 16 + r;
        int row1 = row0 + 8;
        float linv0 = 1.0f / LL[row0];
        float linv1 = 1.0f / LL[row1];
        float s0 = 0.f, q0 = 0.f, s1 = 0.f, q1 = 0.f;
#pragma unroll
        for (int d = 0; d < 4; d++)
#pragma unroll
            for (int nt = 0; nt < 4; nt++) {
                acc[d][nt][0] *= linv0; acc[d][nt][1] *= linv0;
                acc[d][nt][2] *= linv1; acc[d][nt][3] *= linv1;
                s0 += acc[d][nt][0] + acc[d][nt][1];
                q0 += acc[d][nt][0] * acc[d][nt][0] + acc[d][nt][1] * acc[d][nt][1];
                s1 += acc[d][nt][2] + acc[d][nt][3];
                q1 += acc[d][nt][2] * acc[d][nt][2] + acc[d][nt][3] * acc[d][nt][3];
            }
#pragma unroll
        for (int off = 1; off < 4; off <<= 1) {
            s0 += __shfl_xor_sync(0xffffffffu, s0, off);
            q0 += __shfl_xor_sync(0xffffffffu, q0, off);
            s1 += __shfl_xor_sync(0xffffffffu, s1, off);
            q1 += __shfl_xor_sync(0xffffffffu, q1, off);
        }
        if ((lane & 3) == 0) {
            RS[row0 * 4 + vg] = s0;  RQ[row0 * 4 + vg] = q0;
            RS[row1 * 4 + vg] = s1;  RQ[row1 * 4 + vg] = q1;
        }
        __syncthreads();
        float ts0 = RS[row0 * 4] + RS[row0 * 4 + 1] + RS[row0 * 4 + 2] + RS[row0 * 4 + 3];
        float tq0 = RQ[row0 * 4] + RQ[row0 * 4 + 1] + RQ[row0 * 4 + 2] + RQ[row0 * 4 + 3];
        float ts1 = RS[row1 * 4] + RS[row1 * 4 + 1] + RS[row1 * 4 + 2] + RS[row1 * 4 + 3];
        float tq1 = RQ[row1 * 4] + RQ[row1 * 4 + 1] + RQ[row1 * 4 + 2] + RQ[row1 * 4 + 3];
        const float invD = 1.0f / (float)DIM;
        float mu0 = ts0 * invD, var0 = tq0 * invD - mu0 * mu0;
        float mu1 = ts1 * invD, var1 = tq1 * invD - mu1 * mu1;
        float rstd0 = rsqrtf(var0 + 1e-5f);
        float rstd1 = rsqrtf(var1 + 1e-5f);

        size_t ob0 = (qrow0 + row0) * 512;
        size_t ob1 = (qrow0 + row1) * 512;
#pragma unroll
        for (int d = 0; d < 4; d++)
#pragma unroll
            for (int nt = 0; nt < 4; nt++) {
                int col = d * 128 + vg * 32 + nt * 8 + c2;
                float g0 = gamma[col], g1 = gamma[col + 1];
                float be0 = beta[col], be1 = beta[col + 1];
                float2 o0 = make_float2((acc[d][nt][0] - mu0) * rstd0 * g0 + be0,
                                        (acc[d][nt][1] - mu0) * rstd0 * g1 + be1);
                float2 o1 = make_float2((acc[d][nt][2] - mu1) * rstd1 * g0 + be0,
                                        (acc[d][nt][3] - mu1) * rstd1 * g1 + be1);
                *(float2*)(out + ob0 + col) = o0;
                *(float2*)(out + ob1 + col) = o1;
            }
    }
}

// ---------------------------------------------------------------------------
// Launch
// ---------------------------------------------------------------------------
extern "C" void kernel_launch(void* const* d_in, const int* in_sizes, int n_in,
                              void* d_out, int out_size)
{
    const float* x0    = (const float*)d_in[0];
    const float* x1    = (const float*)d_in[1];
    const float* Wq    = (const float*)d_in[2];
    const float* Wk    = (const float*)d_in[3];
    const float* Wv    = (const float*)d_in[4];
    const float* gamma = (const float*)d_in[5];
    const float* beta  = (const float*)d_in[6];
    float* out = (float*)d_out;

    cudaFuncSetAttribute(qkv_hmma, cudaFuncAttributeMaxDynamicSharedMemorySize, GB_SMEM);
    cudaFuncSetAttribute(attn_mma, cudaFuncAttributeMaxDynamicSharedMemorySize, ATTN_SMEM);

    conv_x<<<MTOT, 256>>>(x0, x1);
    conv_w<<<dim3(16, 32, 3), dim3(32, 8)>>>(Wq, Wk, Wv);
    qkv_hmma<<<dim3(12, 128), 256, GB_SMEM>>>();
    attn_mma<<<dim3(SEQ / 64, BATCH), 512, ATTN_SMEM>>>(gamma, beta, out);
}

// round 8
// speedup vs baseline: 3.7533x; 1.0567x over previous
#include <cuda_runtime.h>
#include <cuda_bf16.h>
#include <math.h>

// Problem constants
#define BATCH 8
#define SEQ   2048
#define DIM   512
#define KDIM  1024
#define MTOT  (BATCH*SEQ)   // 16384

// Scratch (no cudaMalloc allowed)
__device__ __nv_bfloat16 g_Ah[(size_t)MTOT * KDIM];
__device__ __nv_bfloat16 g_Al[(size_t)MTOT * KDIM];
__device__ __nv_bfloat16 g_Wh[(size_t)3 * DIM * KDIM];
__device__ __nv_bfloat16 g_Wl[(size_t)3 * DIM * KDIM];
__device__ __nv_bfloat16 g_qh[(size_t)MTOT * DIM];
__device__ __nv_bfloat16 g_ql[(size_t)MTOT * DIM];
__device__ __nv_bfloat16 g_kh[(size_t)MTOT * DIM];
__device__ __nv_bfloat16 g_kl[(size_t)MTOT * DIM];
__device__ __nv_bfloat16 g_vh[(size_t)MTOT * DIM];
__device__ __nv_bfloat16 g_vl[(size_t)MTOT * DIM];

// ---------------------------------------------------------------------------
// helpers
// ---------------------------------------------------------------------------
__device__ __forceinline__ unsigned smem_u32(const void* p) {
    unsigned a;
    asm("{ .reg .u64 t; cvta.to.shared.u64 t, %1; cvt.u32.u64 %0, t; }" : "=r"(a) : "l"(p));
    return a;
}
__device__ __forceinline__ void cpa16(unsigned dst, const void* src) {
    asm volatile("cp.async.cg.shared.global [%0], [%1], 16;"
                 :: "r"(dst), "l"(__cvta_generic_to_global(src)) : "memory");
}
__device__ __forceinline__ void cp_commit() {
    asm volatile("cp.async.commit_group;" ::: "memory");
}
template <int N>
__device__ __forceinline__ void cp_wait() {
    asm volatile("cp.async.wait_group %0;" :: "n"(N) : "memory");
}
__device__ __forceinline__ void ldsm4(unsigned* r, unsigned addr) {
    asm volatile("ldmatrix.sync.aligned.m8n8.x4.shared.b16 {%0,%1,%2,%3}, [%4];"
                 : "=r"(r[0]), "=r"(r[1]), "=r"(r[2]), "=r"(r[3]) : "r"(addr));
}
__device__ __forceinline__ void ldsm4t(unsigned* r, unsigned addr) {
    asm volatile("ldmatrix.sync.aligned.m8n8.x4.trans.shared.b16 {%0,%1,%2,%3}, [%4];"
                 : "=r"(r[0]), "=r"(r[1]), "=r"(r[2]), "=r"(r[3]) : "r"(addr));
}
__device__ __forceinline__ void mma_bf16(float* c, const unsigned* a,
                                         unsigned b0, unsigned b1) {
    asm volatile(
        "mma.sync.aligned.m16n8k16.row.col.f32.bf16.bf16.f32 "
        "{%0,%1,%2,%3}, {%4,%5,%6,%7}, {%8,%9}, {%0,%1,%2,%3};"
        : "+f"(c[0]), "+f"(c[1]), "+f"(c[2]), "+f"(c[3])
        : "r"(a[0]), "r"(a[1]), "r"(a[2]), "r"(a[3]), "r"(b0), "r"(b1));
}

// ---------------------------------------------------------------------------
// Conversion: x0|x1 -> bf16 hi/lo, row-major [MTOT][1024]
// ---------------------------------------------------------------------------
__global__ __launch_bounds__(256)
void conv_x(const float* __restrict__ x0, const float* __restrict__ x1)
{
    unsigned t = blockIdx.x * 256u + threadIdx.x;
    unsigned m  = t >> 8;
    unsigned k4 = (t & 255u) * 4u;
    float4 v = (k4 < 512u)
        ? *(const float4*)(x0 + (size_t)m * 512 + k4)
        : *(const float4*)(x1 + (size_t)m * 512 + (k4 - 512u));
    __nv_bfloat16 h0 = __float2bfloat16(v.x);
    __nv_bfloat16 h1 = __float2bfloat16(v.y);
    __nv_bfloat16 h2 = __float2bfloat16(v.z);
    __nv_bfloat16 h3 = __float2bfloat16(v.w);
    __nv_bfloat16 l0 = __float2bfloat16(v.x - __bfloat162float(h0));
    __nv_bfloat16 l1 = __float2bfloat16(v.y - __bfloat162float(h1));
    __nv_bfloat16 l2 = __float2bfloat16(v.z - __bfloat162float(h2));
    __nv_bfloat16 l3 = __float2bfloat16(v.w - __bfloat162float(h3));
    size_t o = (size_t)m * 1024 + k4;
    __nv_bfloat162* dh = (__nv_bfloat162*)(g_Ah + o);
    __nv_bfloat162* dl = (__nv_bfloat162*)(g_Al + o);
    dh[0] = __nv_bfloat162(h0, h1); dh[1] = __nv_bfloat162(h2, h3);
    dl[0] = __nv_bfloat162(l0, l1); dl[1] = __nv_bfloat162(l2, l3);
}

// ---------------------------------------------------------------------------
// W[k][n] -> W^T hi/lo bf16, n-major rows (q scaled by 1/sqrt(D))
// ---------------------------------------------------------------------------
__global__ __launch_bounds__(256)
void conv_w(const float* __restrict__ Wq, const float* __restrict__ Wk,
            const float* __restrict__ Wv)
{
    __shared__ float tile[32][33];
    const int z  = blockIdx.z;
    const float* __restrict__ W = (z == 0) ? Wq : ((z == 1) ? Wk : Wv);
    const int n0 = blockIdx.x * 32;
    const int k0 = blockIdx.y * 32;
    const int tx = threadIdx.x;
    const int ty = threadIdx.y;

    for (int r = ty; r < 32; r += 8)
        tile[r][tx] = W[(size_t)(k0 + r) * 512 + n0 + tx];
    __syncthreads();

    const float scale = (z == 0) ? 0.04419417382415922f : 1.0f;
    for (int r = ty; r < 32; r += 8) {
        int n = n0 + r;
        int k = k0 + tx;
        float v = tile[tx][r] * scale;
        __nv_bfloat16 hi = __float2bfloat16(v);
        __nv_bfloat16 lo = __float2bfloat16(v - __bfloat162float(hi));
        size_t idx = ((size_t)(z * 512 + n)) * 1024 + k;
        g_Wh[idx] = hi;
        g_Wl[idx] = lo;
    }
}

// ---------------------------------------------------------------------------
// QKV GEMM via mma.sync bf16 split-2. Epilogue stores bf16 hi/lo q/k/v.
// ---------------------------------------------------------------------------
#define GB_BUF 40960
#define GB_SMEM (2 * GB_BUF)

__device__ __forceinline__ void gemm_issue(unsigned sb, int buf, int m0, int nbase,
                                           int k0, int tid)
{
    const int lr  = tid >> 1;
    const int lc0 = (tid & 1) * 2;
    unsigned base = sb + buf * GB_BUF;
    const __nv_bfloat16* pa_h = g_Ah + (size_t)(m0 + lr) * 1024 + k0;
    const __nv_bfloat16* pa_l = g_Al + (size_t)(m0 + lr) * 1024 + k0;
    const __nv_bfloat16* pb_h = g_Wh + (size_t)(nbase + lr) * 1024 + k0;
    const __nv_bfloat16* pb_l = g_Wl + (size_t)(nbase + lr) * 1024 + k0;
#pragma unroll
    for (int cc = 0; cc < 2; cc++) {
        int c = lc0 + cc;
        unsigned o = lr * 80 + c * 16;
        cpa16(base + o,          pa_h + c * 8);
        cpa16(base + 10240 + o,  pa_l + c * 8);
        cpa16(base + 20480 + o,  pb_h + c * 8);
        cpa16(base + 30720 + o,  pb_l + c * 8);
    }
    cp_commit();
}

__global__ __launch_bounds__(256, 2)
void qkv_hmma()
{
    extern __shared__ char smem[];
    unsigned sb = smem_u32(smem);
    const int tid  = threadIdx.x;
    const int lane = tid & 31;
    const int w    = tid >> 5;
    const int wm   = w >> 2;
    const int wn   = w & 3;
    const int nbase = blockIdx.x * 128;
    const int m0    = blockIdx.y * 128;

    float acc[4][4][4];
#pragma unroll
    for (int i = 0; i < 4; i++)
#pragma unroll
        for (int j = 0; j < 4; j++)
#pragma unroll
            for (int k = 0; k < 4; k++) acc[i][j][k] = 0.0f;

    const int mrowA = (lane & 7) + ((lane >> 3) & 1) * 8;
    const int kcA   = (lane >> 4) & 1;
    const int nrowB = (lane & 7) + ((lane >> 4) & 1) * 8;
    const int kcB   = (lane >> 3) & 1;
    const unsigned aoff = (wm * 64 + mrowA) * 80 + kcA * 16;
    const unsigned boff = 20480u + (wn * 32 + nrowB) * 80 + kcB * 16;

    gemm_issue(sb, 0, m0, nbase, 0, tid);

    for (int ch = 0; ch < 32; ++ch) {
        if (ch + 1 < 32) {
            gemm_issue(sb, (ch + 1) & 1, m0, nbase, (ch + 1) * 32, tid);
            cp_wait<1>();
        } else {
            cp_wait<0>();
        }
        __syncthreads();

        unsigned base = sb + (ch & 1) * GB_BUF;
#pragma unroll
        for (int ks = 0; ks < 2; ks++) {
            unsigned Bh[8], Bl[8];
            ldsm4(&Bh[0], base + boff + ks * 32);
            ldsm4(&Bh[4], base + boff + 16 * 80 + ks * 32);
            ldsm4(&Bl[0], base + boff + 10240 + ks * 32);
            ldsm4(&Bl[4], base + boff + 10240 + 16 * 80 + ks * 32);
#pragma unroll
            for (int mt = 0; mt < 4; mt++) {
                unsigned Ah[4], Al[4];
                ldsm4(Ah, base + aoff + mt * (16 * 80) + ks * 32);
                ldsm4(Al, base + aoff + 10240 + mt * (16 * 80) + ks * 32);
#pragma unroll
                for (int nt = 0; nt < 4; nt++) {
                    mma_bf16(acc[mt][nt], Ah, Bh[nt * 2], Bh[nt * 2 + 1]);
                    mma_bf16(acc[mt][nt], Ah, Bl[nt * 2], Bl[nt * 2 + 1]);
                    mma_bf16(acc[mt][nt], Al, Bh[nt * 2], Bh[nt * 2 + 1]);
                }
            }
        }
        __syncthreads();
    }

    // Epilogue: fp32 acc -> bf16 hi/lo stores
    const int z = nbase >> 9;
    __nv_bfloat16* Xh = (z == 0) ? g_qh : ((z == 1) ? g_kh : g_vh);
    __nv_bfloat16* Xl = (z == 0) ? g_ql : ((z == 1) ? g_kl : g_vl);
    const int colb = (nbase & 511) + wn * 32;
    const int gid = lane >> 2, tig = lane & 3;
#pragma unroll
    for (int mt = 0; mt < 4; mt++) {
#pragma unroll
        for (int nt = 0; nt < 4; nt++) {
            int row = m0 + wm * 64 + mt * 16 + gid;
            int col = colb + nt * 8 + tig * 2;
#pragma unroll
            for (int rr = 0; rr < 2; rr++) {
                float v0 = acc[mt][nt][rr * 2 + 0];
                float v1 = acc[mt][nt][rr * 2 + 1];
                __nv_bfloat16 h0 = __float2bfloat16(v0);
                __nv_bfloat16 h1 = __float2bfloat16(v1);
                __nv_bfloat16 l0 = __float2bfloat16(v0 - __bfloat162float(h0));
                __nv_bfloat16 l1 = __float2bfloat16(v1 - __bfloat162float(h1));
                size_t o = (size_t)(row + rr * 8) * 512 + col;
                *(__nv_bfloat162*)(Xh + o) = __nv_bfloat162(h0, h1);
                *(__nv_bfloat162*)(Xl + o) = __nv_bfloat162(l0, l1);
            }
        }
    }
}

// ---------------------------------------------------------------------------
// Tensor-core flash attention + fused LayerNorm, 64x64 tiles.
// CTA = (b, 64-row q-tile), 512 threads (16 warps).
// K/V streamed as 64-key x 128-d hi/lo chunks through 2 buffers (1-ahead).
// S phase:  4x4 warp grid, 16 rows x 16 cols each; B frags via single ldsm4.
// softmax:  SIMT (each thread: 2 rows x 4 cols); P overlays S region.
// PV phase: 4x4 warp grid (rh x vg, 32 d-cols/chunk); P frags hoisted to regs.
// ---------------------------------------------------------------------------
#define SD 68        // S pitch fp32 (272B: 16B-multiple => float4 rows)
#define PP 72        // P pitch bf16 (144B = 9*16B, odd => conflict-free ldsm)

#define OQH 0                    /* 64 x 1040B */
#define OQL 66560
#define OCB 133120               /* 2 bufs x 34816 (hi 17408 | lo 17408) */
#define OSP 202752               /* S 64x68 fp32 (17408), overlaid by P */
#define OPH 202752               /* bf16 64x72 = 9216 */
#define OPL 211968
#define OAL 221184               /* fp32 64 */
#define OLL 221440               /* fp32 64 */
#define ORS 221696               /* fp32 64x4 */
#define ORQ 222720               /* fp32 64x4 */
#define ATTN_SMEM 223744

#define NEG_INF __int_as_float(0xff800000)

// Load one 64-key x 128-d hi/lo chunk of K or V into buffer `buf`.
// 64 rows x 16 x 16B units x {hi,lo} = 2048 cp.async (4 per thread).
__device__ __forceinline__ void attn_load_chunk(unsigned sb, int buf,
                                                const __nv_bfloat16* Xh,
                                                const __nv_bfloat16* Xl,
                                                size_t srow0, int dc, int tid)
{
#pragma unroll
    for (int i = 0; i < 4; i++) {
        int idx = tid + i * 512;          // 0..2047
        int which = idx >> 10;            // 0:hi 1:lo
        int u = idx & 1023;
        int row = u >> 4;                 // 0..63 (key)
        int c = u & 15;                   // 16B unit within 128 d (256B)
        const __nv_bfloat16* src = (which ? Xl : Xh) + (srow0 + row) * 512 + dc * 128 + c * 8;
        unsigned dst = sb + OCB + buf * 34816 + which * 17408 + row * 272 + c * 16;
        cpa16(dst, src);
    }
    cp_commit();
}

__global__ __launch_bounds__(512, 1)
void attn_mma(const float* __restrict__ gamma, const float* __restrict__ beta,
              float* __restrict__ out)
{
    extern __shared__ char smc[];
    unsigned sb = smem_u32(smc);
    float* S    = (float*)(smc + OSP);
    float* AL   = (float*)(smc + OAL);
    float* LL   = (float*)(smc + OLL);
    float* RS   = (float*)(smc + ORS);
    float* RQ   = (float*)(smc + ORQ);
    __nv_bfloat16* PH = (__nv_bfloat16*)(smc + OPH);
    __nv_bfloat16* PL = (__nv_bfloat16*)(smc + OPL);

    const int b   = blockIdx.y;
    const int qb  = gridDim.x - 1 - blockIdx.x;     // heavy tiles first
    const int tid = threadIdx.x;
    const int lane = tid & 31;
    const int w    = tid >> 5;      // 0..15
    const int rh   = w >> 2;        // row group (16 rows)
    const int cg   = w & 3;         // S col group (16 cols)
    const int vg   = w & 3;         // PV col group (32 d-cols per chunk)
    const int ti = tid >> 4;        // 0..31 -> rows 2ti, 2ti+1
    const int tj = tid & 15;        // cols 4tj..4tj+3

    const size_t qrow0 = (size_t)b * SEQ + (size_t)qb * 64;

    // --- load Q (64 x 512 hi/lo) ---
#pragma unroll
    for (int i = 0; i < 16; i++) {
        int idx = tid + i * 512;
        int which = idx >> 12;
        int u = idx & 4095;
        int row = u >> 6;
        int c = u & 63;
        const __nv_bfloat16* src = (which ? g_ql : g_qh) + (qrow0 + row) * 512 + c * 8;
        unsigned dst = sb + (which ? OQL : OQH) + row * 1040 + c * 16;
        cpa16(dst, src);
    }
    cp_commit();

    float acc[4][4][4];
#pragma unroll
    for (int d = 0; d < 4; d++)
#pragma unroll
        for (int nt = 0; nt < 4; nt++)
#pragma unroll
            for (int k = 0; k < 4; k++) acc[d][nt][k] = 0.0f;

    float m0r = NEG_INF, m1r = NEG_INF;
    float l0r = 0.0f,    l1r = 0.0f;

    // ldmatrix lane components
    const unsigned qrow_a = rh * 16 + (lane & 7) + ((lane >> 3) & 1) * 8;
    const unsigned kca    = ((lane >> 4) & 1) * 8;
    const unsigned krow4  = cg * 16 + ((lane >> 4) & 1) * 8 + (lane & 7);
    const unsigned kc4    = ((lane >> 3) & 1) * 8;
    const unsigned prow_a = qrow_a;
    const unsigned psel   = ((lane >> 4) & 1) * 8;
    const unsigned vsrow  = ((lane >> 3) & 1) * 8 + (lane & 7);
    const unsigned vdoff  = ((lane >> 4) & 1) * 8;

    // prologue: prefetch K chunks 0,1 of jb=0
    attn_load_chunk(sb, 0, g_kh, g_kl, (size_t)b * SEQ, 0, tid);
    attn_load_chunk(sb, 1, g_kh, g_kl, (size_t)b * SEQ, 1, tid);

    for (int jb = 0; jb <= qb; jb++) {
        const size_t srow0 = (size_t)b * SEQ + (size_t)jb * 64;
        const bool last = (jb == qb);

        // ---- S phase: S(64x64) = Q Kt over 4 d-chunks ----
        float s0a[2][4] = {{0,0,0,0},{0,0,0,0}};   // Ah·Bh + Ah·Bl
        float s1a[2][4] = {{0,0,0,0},{0,0,0,0}};   // Al·Bh
#pragma unroll
        for (int dc = 0; dc < 4; dc++) {
            cp_wait<1>();
            __syncthreads();
            unsigned kb = sb + OCB + (dc & 1) * 34816;
#pragma unroll
            for (int ks = 0; ks < 8; ks++) {
                unsigned qcol = (dc * 128 + ks * 16 + kca) * 2;
                unsigned Ah[4], Alo[4], Bh4[4], Bl4[4];
                ldsm4(Ah,  sb + OQH + qrow_a * 1040 + qcol);
                ldsm4(Alo, sb + OQL + qrow_a * 1040 + qcol);
                unsigned kcol = (ks * 16 + kc4) * 2;
                ldsm4(Bh4, kb + krow4 * 272 + kcol);
                ldsm4(Bl4, kb + 17408 + krow4 * 272 + kcol);
                mma_bf16(s0a[0], Ah,  Bh4[0], Bh4[1]);
                mma_bf16(s0a[1], Ah,  Bh4[2], Bh4[3]);
                mma_bf16(s1a[0], Alo, Bh4[0], Bh4[1]);
                mma_bf16(s1a[1], Alo, Bh4[2], Bh4[3]);
                mma_bf16(s0a[0], Ah,  Bl4[0], Bl4[1]);
                mma_bf16(s0a[1], Ah,  Bl4[2], Bl4[3]);
            }
            if (dc == 3) {
                // write S fragments before the buffer-release sync
                int r  = lane >> 2;
                int c2 = (lane & 3) * 2;
                int row0 = rh * 16 + r;
#pragma unroll
                for (int nt2 = 0; nt2 < 2; nt2++) {
                    int col = cg * 16 + nt2 * 8 + c2;
                    *(float2*)&S[row0 * SD + col] =
                        make_float2(s0a[nt2][0] + s1a[nt2][0], s0a[nt2][1] + s1a[nt2][1]);
                    *(float2*)&S[(row0 + 8) * SD + col] =
                        make_float2(s0a[nt2][2] + s1a[nt2][2], s0a[nt2][3] + s1a[nt2][3]);
                }
            }
            __syncthreads();
            if (dc < 2)
                attn_load_chunk(sb, dc & 1, g_kh, g_kl, srow0, dc + 2, tid);
            else
                attn_load_chunk(sb, dc & 1, g_vh, g_vl, srow0, dc - 2, tid);
        }

        // ---- softmax (each thread: rows 2ti,2ti+1 x cols 4tj..4tj+3) ----
        {
            float4 v0 = *(float4*)&S[(2 * ti) * SD + 4 * tj];
            float4 v1 = *(float4*)&S[(2 * ti + 1) * SD + 4 * tj];
            float a0[4] = {v0.x, v0.y, v0.z, v0.w};
            float a1[4] = {v1.x, v1.y, v1.z, v1.w};

            if (jb == qb) {
                int row0 = 2 * ti, colb = 4 * tj;
#pragma unroll
                for (int c = 0; c < 4; c++) {
                    if (colb + c > row0)     a0[c] = NEG_INF;
                    if (colb + c > row0 + 1) a1[c] = NEG_INF;
                }
            }

            float r0 = fmaxf(fmaxf(a0[0], a0[1]), fmaxf(a0[2], a0[3]));
            float r1 = fmaxf(fmaxf(a1[0], a1[1]), fmaxf(a1[2], a1[3]));
#pragma unroll
            for (int off = 1; off < 16; off <<= 1) {
                r0 = fmaxf(r0, __shfl_xor_sync(0xffffffffu, r0, off));
                r1 = fmaxf(r1, __shfl_xor_sync(0xffffffffu, r1, off));
            }
            float mn0 = fmaxf(m0r, r0);
            float mn1 = fmaxf(m1r, r1);
            float al0 = __expf(m0r - mn0);
            float al1 = __expf(m1r - mn1);

            float p0[4], p1[4];
#pragma unroll
            for (int c = 0; c < 4; c++) {
                p0[c] = __expf(a0[c] - mn0);
                p1[c] = __expf(a1[c] - mn1);
            }
            float rs0 = (p0[0] + p0[1]) + (p0[2] + p0[3]);
            float rs1 = (p1[0] + p1[1]) + (p1[2] + p1[3]);
#pragma unroll
            for (int off = 1; off < 16; off <<= 1) {
                rs0 += __shfl_xor_sync(0xffffffffu, rs0, off);
                rs1 += __shfl_xor_sync(0xffffffffu, rs1, off);
            }
            l0r = al0 * l0r + rs0;  m0r = mn0;
            l1r = al1 * l1r + rs1;  m1r = mn1;

            if (tj == 0) {
                AL[2 * ti]     = al0;
                AL[2 * ti + 1] = al1;
                LL[2 * ti]     = l0r;
                LL[2 * ti + 1] = l1r;
            }
            __syncthreads();   // all S reads done before P overlays S

            __nv_bfloat16 h0[4], h1[4];
#pragma unroll
            for (int c = 0; c < 4; c++) {
                h0[c] = __float2bfloat16(p0[c]);
                h1[c] = __float2bfloat16(p1[c]);
            }
            *(__nv_bfloat162*)&PH[(2 * ti) * PP + 4 * tj]         = __nv_bfloat162(h0[0], h0[1]);
            *(__nv_bfloat162*)&PH[(2 * ti) * PP + 4 * tj + 2]     = __nv_bfloat162(h0[2], h0[3]);
            *(__nv_bfloat162*)&PH[(2 * ti + 1) * PP + 4 * tj]     = __nv_bfloat162(h1[0], h1[1]);
            *(__nv_bfloat162*)&PH[(2 * ti + 1) * PP + 4 * tj + 2] = __nv_bfloat162(h1[2], h1[3]);
            *(__nv_bfloat162*)&PL[(2 * ti) * PP + 4 * tj] = __nv_bfloat162(
                __float2bfloat16(p0[0] - __bfloat162float(h0[0])),
                __float2bfloat16(p0[1] - __bfloat162float(h0[1])));
            *(__nv_bfloat162*)&PL[(2 * ti) * PP + 4 * tj + 2] = __nv_bfloat162(
                __float2bfloat16(p0[2] - __bfloat162float(h0[2])),
                __float2bfloat16(p0[3] - __bfloat162float(h0[3])));
            *(__nv_bfloat162*)&PL[(2 * ti + 1) * PP + 4 * tj] = __nv_bfloat162(
                __float2bfloat16(p1[0] - __bfloat162float(h1[0])),
                __float2bfloat16(p1[1] - __bfloat162float(h1[1])));
            *(__nv_bfloat162*)&PL[(2 * ti + 1) * PP + 4 * tj + 2] = __nv_bfloat162(
                __float2bfloat16(p1[2] - __bfloat162float(h1[2])),
                __float2bfloat16(p1[3] - __bfloat162float(h1[3])));
        }
        __syncthreads();   // P + AL visible

        // hoist P fragments (whole 64-key tile) into registers
        unsigned Phf[4][4], Plf[4][4];
#pragma unroll
        for (int ks2 = 0; ks2 < 4; ks2++) {
            unsigned pcol = (ks2 * 16 + psel) * 2;
            ldsm4(Phf[ks2], sb + OPH + prow_a * 144 + pcol);
            ldsm4(Plf[ks2], sb + OPL + prow_a * 144 + pcol);
        }

        // scale accumulators by alpha
        {
            float a0 = AL[rh * 16 + (lane >> 2)];
            float a1 = AL[rh * 16 + (lane >> 2) + 8];
#pragma unroll
            for (int d = 0; d < 4; d++)
#pragma unroll
                for (int nt = 0; nt < 4; nt++) {
                    acc[d][nt][0] *= a0; acc[d][nt][1] *= a0;
                    acc[d][nt][2] *= a1; acc[d][nt][3] *= a1;
                }
        }

        // ---- PV phase over 4 streamed V chunks ----
#pragma unroll
        for (int dc = 0; dc < 4; dc++) {
            if (last && dc == 3) cp_wait<0>(); else cp_wait<1>();
            __syncthreads();
            unsigned vb = sb + OCB + (dc & 1) * 34816;
#pragma unroll
            for (int ks2 = 0; ks2 < 4; ks2++) {
                unsigned vrow = (ks2 * 16 + vsrow) * 272;
#pragma unroll
                for (int ng2 = 0; ng2 < 2; ng2++) {
                    unsigned vcol = (vg * 32 + ng2 * 16 + vdoff) * 2;
                    unsigned Bh[4], Bl[4];
                    ldsm4t(Bh, vb + vrow + vcol);
                    ldsm4t(Bl, vb + 17408 + vrow + vcol);
                    int nt0 = ng2 * 2, nt1 = ng2 * 2 + 1;
                    mma_bf16(acc[dc][nt0], Phf[ks2], Bh[0], Bh[1]);
                    mma_bf16(acc[dc][nt0], Plf[ks2], Bh[0], Bh[1]);
                    mma_bf16(acc[dc][nt0], Phf[ks2], Bl[0], Bl[1]);
                    mma_bf16(acc[dc][nt1], Phf[ks2], Bh[2], Bh[3]);
                    mma_bf16(acc[dc][nt1], Plf[ks2], Bh[2], Bh[3]);
                    mma_bf16(acc[dc][nt1], Phf[ks2], Bl[2], Bl[3]);
                }
            }
            __syncthreads();
            if (dc < 2)
                attn_load_chunk(sb, dc & 1, g_vh, g_vl, srow0, dc + 2, tid);
            else if (!last)
                attn_load_chunk(sb, dc & 1, g_kh, g_kl, srow0 + 64, dc - 2, tid);
        }
    }

    // ---- epilogue: 1/l, LayerNorm, store ----
    {
        int r  = lane >> 2;
        int c2 = (lane & 3) * 2;
        int row0 = rh * 16 + r;
        int row1 = row0 + 8;
        float linv0 = 1.0f / LL[row0];
        float linv1 = 1.0f / LL[row1];
        float s0 = 0.f, q0 = 0.f, s1 = 0.f, q1 = 0.f;
#pragma unroll
        for (int d = 0; d < 4; d++)
#pragma unroll
            for (int nt = 0; nt < 4; nt++) {
                acc[d][nt][0] *= linv0; acc[d][nt][1] *= linv0;
                acc[d][nt][2] *= linv1; acc[d][nt][3] *= linv1;
                s0 += acc[d][nt][0] + acc[d][nt][1];
                q0 += acc[d][nt][0] * acc[d][nt][0] + acc[d][nt][1] * acc[d][nt][1];
                s1 += acc[d][nt][2] + acc[d][nt][3];
                q1 += acc[d][nt][2] * acc[d][nt][2] + acc[d][nt][3] * acc[d][nt][3];
            }
#pragma unroll
        for (int off = 1; off < 4; off <<= 1) {
            s0 += __shfl_xor_sync(0xffffffffu, s0, off);
            q0 += __shfl_xor_sync(0xffffffffu, q0, off);
            s1 += __shfl_xor_sync(0xffffffffu, s1, off);
            q1 += __shfl_xor_sync(0xffffffffu, q1, off);
        }
        if ((lane & 3) == 0) {
            RS[row0 * 4 + vg] = s0;  RQ[row0 * 4 + vg] = q0;
            RS[row1 * 4 + vg] = s1;  RQ[row1 * 4 + vg] = q1;
        }
        __syncthreads();
        float ts0 = RS[row0 * 4] + RS[row0 * 4 + 1] + RS[row0 * 4 + 2] + RS[row0 * 4 + 3];
        float tq0 = RQ[row0 * 4] + RQ[row0 * 4 + 1] + RQ[row0 * 4 + 2] + RQ[row0 * 4 + 3];
        float ts1 = RS[row1 * 4] + RS[row1 * 4 + 1] + RS[row1 * 4 + 2] + RS[row1 * 4 + 3];
        float tq1 = RQ[row1 * 4] + RQ[row1 * 4 + 1] + RQ[row1 * 4 + 2] + RQ[row1 * 4 + 3];
        const float invD = 1.0f / (float)DIM;
        float mu0 = ts0 * invD, var0 = tq0 * invD - mu0 * mu0;
        float mu1 = ts1 * invD, var1 = tq1 * invD - mu1 * mu1;
        float rstd0 = rsqrtf(var0 + 1e-5f);
        float rstd1 = rsqrtf(var1 + 1e-5f);

        size_t ob0 = (qrow0 + row0) * 512;
        size_t ob1 = (qrow0 + row1) * 512;
#pragma unroll
        for (int d = 0; d < 4; d++)
#pragma unroll
            for (int nt = 0; nt < 4; nt++) {
                int col = d * 128 + vg * 32 + nt * 8 + c2;
                float g0 = gamma[col], g1 = gamma[col + 1];
                float be0 = beta[col], be1 = beta[col + 1];
                float2 o0 = make_float2((acc[d][nt][0] - mu0) * rstd0 * g0 + be0,
                                        (acc[d][nt][1] - mu0) * rstd0 * g1 + be1);
                float2 o1 = make_float2((acc[d][nt][2] - mu1) * rstd1 * g0 + be0,
                                        (acc[d][nt][3] - mu1) * rstd1 * g1 + be1);
                *(float2*)(out + ob0 + col) = o0;
                *(float2*)(out + ob1 + col) = o1;
            }
    }
}

// ---------------------------------------------------------------------------
// Launch
// ---------------------------------------------------------------------------
extern "C" void kernel_launch(void* const* d_in, const int* in_sizes, int n_in,
                              void* d_out, int out_size)
{
    const float* x0    = (const float*)d_in[0];
    const float* x1    = (const float*)d_in[1];
    const float* Wq    = (const float*)d_in[2];
    const float* Wk    = (const float*)d_in[3];
    const float* Wv    = (const float*)d_in[4];
    const float* gamma = (const float*)d_in[5];
    const float* beta  = (const float*)d_in[6];
    float* out = (float*)d_out;

    cudaFuncSetAttribute(qkv_hmma, cudaFuncAttributeMaxDynamicSharedMemorySize, GB_SMEM);
    cudaFuncSetAttribute(attn_mma, cudaFuncAttributeMaxDynamicSharedMemorySize, ATTN_SMEM);

    conv_x<<<MTOT, 256>>>(x0, x1);
    conv_w<<<dim3(16, 32, 3), dim3(32, 8)>>>(Wq, Wk, Wv);
    qkv_hmma<<<dim3(12, 128), 256, GB_SMEM>>>();
    attn_mma<<<dim3(SEQ / 64, BATCH), 512, ATTN_SMEM>>>(gamma, beta, out);
}

// round 9
// speedup vs baseline: 3.8718x; 1.0316x over previous
#include <cuda_runtime.h>
#include <cuda_bf16.h>
#include <math.h>

// Problem constants
#define BATCH 8
#define SEQ   2048
#define DIM   512
#define KDIM  1024
#define MTOT  (BATCH*SEQ)   // 16384

// Scratch (no cudaMalloc allowed)
__device__ __nv_bfloat16 g_Ah[(size_t)MTOT * KDIM];
__device__ __nv_bfloat16 g_Al[(size_t)MTOT * KDIM];
__device__ __nv_bfloat16 g_Wh[(size_t)3 * DIM * KDIM];
__device__ __nv_bfloat16 g_Wl[(size_t)3 * DIM * KDIM];
__device__ __nv_bfloat16 g_qh[(size_t)MTOT * DIM];
__device__ __nv_bfloat16 g_ql[(size_t)MTOT * DIM];
__device__ __nv_bfloat16 g_kh[(size_t)MTOT * DIM];
__device__ __nv_bfloat16 g_kl[(size_t)MTOT * DIM];
__device__ __nv_bfloat16 g_vh[(size_t)MTOT * DIM];
__device__ __nv_bfloat16 g_vl[(size_t)MTOT * DIM];

// ---------------------------------------------------------------------------
// helpers
// ---------------------------------------------------------------------------
__device__ __forceinline__ unsigned smem_u32(const void* p) {
    unsigned a;
    asm("{ .reg .u64 t; cvta.to.shared.u64 t, %1; cvt.u32.u64 %0, t; }" : "=r"(a) : "l"(p));
    return a;
}
__device__ __forceinline__ void cpa16(unsigned dst, const void* src) {
    asm volatile("cp.async.cg.shared.global [%0], [%1], 16;"
                 :: "r"(dst), "l"(__cvta_generic_to_global(src)) : "memory");
}
__device__ __forceinline__ void cp_commit() {
    asm volatile("cp.async.commit_group;" ::: "memory");
}
template <int N>
__device__ __forceinline__ void cp_wait() {
    asm volatile("cp.async.wait_group %0;" :: "n"(N) : "memory");
}
__device__ __forceinline__ void ldsm4(unsigned* r, unsigned addr) {
    asm volatile("ldmatrix.sync.aligned.m8n8.x4.shared.b16 {%0,%1,%2,%3}, [%4];"
                 : "=r"(r[0]), "=r"(r[1]), "=r"(r[2]), "=r"(r[3]) : "r"(addr));
}
__device__ __forceinline__ void ldsm4t(unsigned* r, unsigned addr) {
    asm volatile("ldmatrix.sync.aligned.m8n8.x4.trans.shared.b16 {%0,%1,%2,%3}, [%4];"
                 : "=r"(r[0]), "=r"(r[1]), "=r"(r[2]), "=r"(r[3]) : "r"(addr));
}
__device__ __forceinline__ void mma_bf16(float* c, const unsigned* a,
                                         unsigned b0, unsigned b1) {
    asm volatile(
        "mma.sync.aligned.m16n8k16.row.col.f32.bf16.bf16.f32 "
        "{%0,%1,%2,%3}, {%4,%5,%6,%7}, {%8,%9}, {%0,%1,%2,%3};"
        : "+f"(c[0]), "+f"(c[1]), "+f"(c[2]), "+f"(c[3])
        : "r"(a[0]), "r"(a[1]), "r"(a[2]), "r"(a[3]), "r"(b0), "r"(b1));
}

// ---------------------------------------------------------------------------
// Conversion: x0|x1 -> bf16 hi/lo, row-major [MTOT][1024]
// ---------------------------------------------------------------------------
__global__ __launch_bounds__(256)
void conv_x(const float* __restrict__ x0, const float* __restrict__ x1)
{
    unsigned t = blockIdx.x * 256u + threadIdx.x;
    unsigned m  = t >> 8;
    unsigned k4 = (t & 255u) * 4u;
    float4 v = (k4 < 512u)
        ? *(const float4*)(x0 + (size_t)m * 512 + k4)
        : *(const float4*)(x1 + (size_t)m * 512 + (k4 - 512u));
    __nv_bfloat16 h0 = __float2bfloat16(v.x);
    __nv_bfloat16 h1 = __float2bfloat16(v.y);
    __nv_bfloat16 h2 = __float2bfloat16(v.z);
    __nv_bfloat16 h3 = __float2bfloat16(v.w);
    __nv_bfloat16 l0 = __float2bfloat16(v.x - __bfloat162float(h0));
    __nv_bfloat16 l1 = __float2bfloat16(v.y - __bfloat162float(h1));
    __nv_bfloat16 l2 = __float2bfloat16(v.z - __bfloat162float(h2));
    __nv_bfloat16 l3 = __float2bfloat16(v.w - __bfloat162float(h3));
    size_t o = (size_t)m * 1024 + k4;
    __nv_bfloat162* dh = (__nv_bfloat162*)(g_Ah + o);
    __nv_bfloat162* dl = (__nv_bfloat162*)(g_Al + o);
    dh[0] = __nv_bfloat162(h0, h1); dh[1] = __nv_bfloat162(h2, h3);
    dl[0] = __nv_bfloat162(l0, l1); dl[1] = __nv_bfloat162(l2, l3);
}

// ---------------------------------------------------------------------------
// W[k][n] -> W^T hi/lo bf16, n-major rows (q scaled by 1/sqrt(D))
// ---------------------------------------------------------------------------
__global__ __launch_bounds__(256)
void conv_w(const float* __restrict__ Wq, const float* __restrict__ Wk,
            const float* __restrict__ Wv)
{
    __shared__ float tile[32][33];
    const int z  = blockIdx.z;
    const float* __restrict__ W = (z == 0) ? Wq : ((z == 1) ? Wk : Wv);
    const int n0 = blockIdx.x * 32;
    const int k0 = blockIdx.y * 32;
    const int tx = threadIdx.x;
    const int ty = threadIdx.y;

    for (int r = ty; r < 32; r += 8)
        tile[r][tx] = W[(size_t)(k0 + r) * 512 + n0 + tx];
    __syncthreads();

    const float scale = (z == 0) ? 0.04419417382415922f : 1.0f;
    for (int r = ty; r < 32; r += 8) {
        int n = n0 + r;
        int k = k0 + tx;
        float v = tile[tx][r] * scale;
        __nv_bfloat16 hi = __float2bfloat16(v);
        __nv_bfloat16 lo = __float2bfloat16(v - __bfloat162float(hi));
        size_t idx = ((size_t)(z * 512 + n)) * 1024 + k;
        g_Wh[idx] = hi;
        g_Wl[idx] = lo;
    }
}

// ---------------------------------------------------------------------------
// QKV GEMM via mma.sync bf16 split-2. Epilogue stores bf16 hi/lo q/k/v.
// ---------------------------------------------------------------------------
#define GB_BUF 40960
#define GB_SMEM (2 * GB_BUF)

__device__ __forceinline__ void gemm_issue(unsigned sb, int buf, int m0, int nbase,
                                           int k0, int tid)
{
    const int lr  = tid >> 1;
    const int lc0 = (tid & 1) * 2;
    unsigned base = sb + buf * GB_BUF;
    const __nv_bfloat16* pa_h = g_Ah + (size_t)(m0 + lr) * 1024 + k0;
    const __nv_bfloat16* pa_l = g_Al + (size_t)(m0 + lr) * 1024 + k0;
    const __nv_bfloat16* pb_h = g_Wh + (size_t)(nbase + lr) * 1024 + k0;
    const __nv_bfloat16* pb_l = g_Wl + (size_t)(nbase + lr) * 1024 + k0;
#pragma unroll
    for (int cc = 0; cc < 2; cc++) {
        int c = lc0 + cc;
        unsigned o = lr * 80 + c * 16;
        cpa16(base + o,          pa_h + c * 8);
        cpa16(base + 10240 + o,  pa_l + c * 8);
        cpa16(base + 20480 + o,  pb_h + c * 8);
        cpa16(base + 30720 + o,  pb_l + c * 8);
    }
    cp_commit();
}

__global__ __launch_bounds__(256, 2)
void qkv_hmma()
{
    extern __shared__ char smem[];
    unsigned sb = smem_u32(smem);
    const int tid  = threadIdx.x;
    const int lane = tid & 31;
    const int w    = tid >> 5;
    const int wm   = w >> 2;
    const int wn   = w & 3;
    const int nbase = blockIdx.x * 128;
    const int m0    = blockIdx.y * 128;

    float acc[4][4][4];
#pragma unroll
    for (int i = 0; i < 4; i++)
#pragma unroll
        for (int j = 0; j < 4; j++)
#pragma unroll
            for (int k = 0; k < 4; k++) acc[i][j][k] = 0.0f;

    const int mrowA = (lane & 7) + ((lane >> 3) & 1) * 8;
    const int kcA   = (lane >> 4) & 1;
    const int nrowB = (lane & 7) + ((lane >> 4) & 1) * 8;
    const int kcB   = (lane >> 3) & 1;
    const unsigned aoff = (wm * 64 + mrowA) * 80 + kcA * 16;
    const unsigned boff = 20480u + (wn * 32 + nrowB) * 80 + kcB * 16;

    gemm_issue(sb, 0, m0, nbase, 0, tid);

    for (int ch = 0; ch < 32; ++ch) {
        if (ch + 1 < 32) {
            gemm_issue(sb, (ch + 1) & 1, m0, nbase, (ch + 1) * 32, tid);
            cp_wait<1>();
        } else {
            cp_wait<0>();
        }
        __syncthreads();

        unsigned base = sb + (ch & 1) * GB_BUF;
#pragma unroll
        for (int ks = 0; ks < 2; ks++) {
            unsigned Bh[8], Bl[8];
            ldsm4(&Bh[0], base + boff + ks * 32);
            ldsm4(&Bh[4], base + boff + 16 * 80 + ks * 32);
            ldsm4(&Bl[0], base + boff + 10240 + ks * 32);
            ldsm4(&Bl[4], base + boff + 10240 + 16 * 80 + ks * 32);
#pragma unroll
            for (int mt = 0; mt < 4; mt++) {
                unsigned Ah[4], Al[4];
                ldsm4(Ah, base + aoff + mt * (16 * 80) + ks * 32);
                ldsm4(Al, base + aoff + 10240 + mt * (16 * 80) + ks * 32);
#pragma unroll
                for (int nt = 0; nt < 4; nt++) {
                    mma_bf16(acc[mt][nt], Ah, Bh[nt * 2], Bh[nt * 2 + 1]);
                    mma_bf16(acc[mt][nt], Ah, Bl[nt * 2], Bl[nt * 2 + 1]);
                    mma_bf16(acc[mt][nt], Al, Bh[nt * 2], Bh[nt * 2 + 1]);
                }
            }
        }
        __syncthreads();
    }

    // Epilogue: fp32 acc -> bf16 hi/lo stores
    const int z = nbase >> 9;
    __nv_bfloat16* Xh = (z == 0) ? g_qh : ((z == 1) ? g_kh : g_vh);
    __nv_bfloat16* Xl = (z == 0) ? g_ql : ((z == 1) ? g_kl : g_vl);
    const int colb = (nbase & 511) + wn * 32;
    const int gid = lane >> 2, tig = lane & 3;
#pragma unroll
    for (int mt = 0; mt < 4; mt++) {
#pragma unroll
        for (int nt = 0; nt < 4; nt++) {
            int row = m0 + wm * 64 + mt * 16 + gid;
            int col = colb + nt * 8 + tig * 2;
#pragma unroll
            for (int rr = 0; rr < 2; rr++) {
                float v0 = acc[mt][nt][rr * 2 + 0];
                float v1 = acc[mt][nt][rr * 2 + 1];
                __nv_bfloat16 h0 = __float2bfloat16(v0);
                __nv_bfloat16 h1 = __float2bfloat16(v1);
                __nv_bfloat16 l0 = __float2bfloat16(v0 - __bfloat162float(h0));
                __nv_bfloat16 l1 = __float2bfloat16(v1 - __bfloat162float(h1));
                size_t o = (size_t)(row + rr * 8) * 512 + col;
                *(__nv_bfloat162*)(Xh + o) = __nv_bfloat162(h0, h1);
                *(__nv_bfloat162*)(Xl + o) = __nv_bfloat162(l0, l1);
            }
        }
    }
}

// ---------------------------------------------------------------------------
// Tensor-core flash attention + fused LayerNorm — 2 CTAs/SM version.
// CTA = (b, 32-row q-tile), 256 threads (8 warps), smem 111.3KB => 2 CTAs/SM.
// KV tiles of 64 keys; K/V streamed as 64-key x 64-d hi/lo chunks (8 per op)
// through 2 rotating buffers, 1 chunk lookahead.
// S phase:  2x4 warp grid (16 rows x 16 cols); softmax SIMT (2x4 per thread).
// PV phase: 2x4 warp grid (rh x vg, 16 d-cols/chunk); P frags hoisted per jb.
// ---------------------------------------------------------------------------
#define SD 68        // S pitch fp32
#define PP 72        // P pitch bf16 (144B, odd*16B)

#define OQH 0                    /* 32 x 1040B = 33280 */
#define OQL 33280                /* -> 66560 */
#define OCB 66560                /* 2 bufs x 18432 (hi 9216 | lo 9216) -> 103424 */
#define OSP 103424               /* S 32x68 fp32 (8704), overlaid by P (9216) */
#define OPH 103424
#define OPL 108032
#define OAL 112640               /* fp32 32 */
#define OLL 112768               /* fp32 32 */
#define ORS 112896               /* fp32 32x4 */
#define ORQ 113408               /* fp32 32x4 */
#define ATTN_SMEM 113920

#define NEG_INF __int_as_float(0xff800000)

// Load one 64-key x 64-d hi/lo chunk of K or V into buffer `buf`.
// 64 rows x 8 x 16B units x {hi,lo} = 1024 cp.async (4 per thread @256).
__device__ __forceinline__ void attn_load_chunk(unsigned sb, int buf,
                                                const __nv_bfloat16* Xh,
                                                const __nv_bfloat16* Xl,
                                                size_t srow0, int dc, int tid)
{
#pragma unroll
    for (int i = 0; i < 4; i++) {
        int idx = tid + i * 256;          // 0..1023
        int which = idx >> 9;             // 0:hi 1:lo
        int u = idx & 511;
        int row = u >> 3;                 // 0..63 (key)
        int c = u & 7;                    // 16B unit within 64 d (128B)
        const __nv_bfloat16* src = (which ? Xl : Xh) + (srow0 + row) * 512 + dc * 64 + c * 8;
        unsigned dst = sb + OCB + buf * 18432 + which * 9216 + row * 144 + c * 16;
        cpa16(dst, src);
    }
    cp_commit();
}

__global__ __launch_bounds__(256, 2)
void attn_mma(const float* __restrict__ gamma, const float* __restrict__ beta,
              float* __restrict__ out)
{
    extern __shared__ char smc[];
    unsigned sb = smem_u32(smc);
    float* S    = (float*)(smc + OSP);
    float* AL   = (float*)(smc + OAL);
    float* LL   = (float*)(smc + OLL);
    float* RS   = (float*)(smc + ORS);
    float* RQ   = (float*)(smc + ORQ);
    __nv_bfloat16* PH = (__nv_bfloat16*)(smc + OPH);
    __nv_bfloat16* PL = (__nv_bfloat16*)(smc + OPL);

    const int b   = blockIdx.y;
    const int qb  = gridDim.x - 1 - blockIdx.x;     // heavy tiles first
    const int tid = threadIdx.x;
    const int lane = tid & 31;
    const int w    = tid >> 5;      // 0..7
    const int rh   = w >> 2;        // 0..1 (16-row group)
    const int cg   = w & 3;         // S col group (16 cols)
    const int vg   = w & 3;         // PV col group (16 d-cols per chunk)
    const int ti = tid >> 4;        // 0..15 -> rows 2ti, 2ti+1
    const int tj = tid & 15;        // cols 4tj..4tj+3

    const size_t qrow0 = (size_t)b * SEQ + (size_t)qb * 32;

    // --- load Q (32 x 512 hi/lo): 4096 units / 256 = 16 per thread ---
#pragma unroll
    for (int i = 0; i < 16; i++) {
        int idx = tid + i * 256;
        int which = idx >> 11;            // 0:Qh 1:Ql
        int u = idx & 2047;
        int row = u >> 6;                 // 0..31
        int c = u & 63;
        const __nv_bfloat16* src = (which ? g_ql : g_qh) + (qrow0 + row) * 512 + c * 8;
        unsigned dst = sb + (which ? OQL : OQH) + row * 1040 + c * 16;
        cpa16(dst, src);
    }
    cp_commit();

    // PV accumulator: acc[dc][nt][4] — 16 rows x (dc*64 + vg*16 + nt*8) cols
    float acc[8][2][4];
#pragma unroll
    for (int d = 0; d < 8; d++)
#pragma unroll
        for (int nt = 0; nt < 2; nt++)
#pragma unroll
            for (int k = 0; k < 4; k++) acc[d][nt][k] = 0.0f;

    float m0r = NEG_INF, m1r = NEG_INF;
    float l0r = 0.0f,    l1r = 0.0f;

    // ldmatrix lane components
    const unsigned qrow_a = rh * 16 + (lane & 7) + ((lane >> 3) & 1) * 8;
    const unsigned kca    = ((lane >> 4) & 1) * 8;
    const unsigned krow4  = cg * 16 + ((lane >> 4) & 1) * 8 + (lane & 7);
    const unsigned kc4    = ((lane >> 3) & 1) * 8;
    const unsigned prow_a = qrow_a;
    const unsigned psel   = ((lane >> 4) & 1) * 8;
    const unsigned vsrow  = ((lane >> 3) & 1) * 8 + (lane & 7);
    const unsigned vdoff  = ((lane >> 4) & 1) * 8;

    const int jbmax = qb >> 1;   // 64-key tiles; diagonal tile = jbmax

    // prologue: prefetch K d-chunks 0,1 of jb=0
    attn_load_chunk(sb, 0, g_kh, g_kl, (size_t)b * SEQ, 0, tid);
    attn_load_chunk(sb, 1, g_kh, g_kl, (size_t)b * SEQ, 1, tid);

    for (int jb = 0; jb <= jbmax; jb++) {
        const size_t srow0 = (size_t)b * SEQ + (size_t)jb * 64;
        const bool last = (jb == jbmax);

        // ---- S phase: S(32x64) = Q Kt over 8 d-chunks of 64 ----
        float s0a[2][4] = {{0,0,0,0},{0,0,0,0}};   // Ah·Bh + Ah·Bl
        float s1a[2][4] = {{0,0,0,0},{0,0,0,0}};   // Al·Bh
#pragma unroll
        for (int dc = 0; dc < 8; dc++) {
            cp_wait<1>();
            __syncthreads();
            unsigned kb = sb + OCB + (dc & 1) * 18432;
#pragma unroll
            for (int ks = 0; ks < 4; ks++) {
                unsigned qcol = (dc * 64 + ks * 16 + kca) * 2;
                unsigned Ah[4], Alo[4], Bh4[4], Bl4[4];
                ldsm4(Ah,  sb + OQH + qrow_a * 1040 + qcol);
                ldsm4(Alo, sb + OQL + qrow_a * 1040 + qcol);
                unsigned kcol = (ks * 16 + kc4) * 2;
                ldsm4(Bh4, kb + krow4 * 144 + kcol);
                ldsm4(Bl4, kb + 9216 + krow4 * 144 + kcol);
                mma_bf16(s0a[0], Ah,  Bh4[0], Bh4[1]);
                mma_bf16(s0a[1], Ah,  Bh4[2], Bh4[3]);
                mma_bf16(s1a[0], Alo, Bh4[0], Bh4[1]);
                mma_bf16(s1a[1], Alo, Bh4[2], Bh4[3]);
                mma_bf16(s0a[0], Ah,  Bl4[0], Bl4[1]);
                mma_bf16(s0a[1], Ah,  Bl4[2], Bl4[3]);
            }
            if (dc == 7) {
                int r  = lane >> 2;
                int c2 = (lane & 3) * 2;
                int row0 = rh * 16 + r;
#pragma unroll
                for (int nt2 = 0; nt2 < 2; nt2++) {
                    int col = cg * 16 + nt2 * 8 + c2;
                    *(float2*)&S[row0 * SD + col] =
                        make_float2(s0a[nt2][0] + s1a[nt2][0], s0a[nt2][1] + s1a[nt2][1]);
                    *(float2*)&S[(row0 + 8) * SD + col] =
                        make_float2(s0a[nt2][2] + s1a[nt2][2], s0a[nt2][3] + s1a[nt2][3]);
                }
            }
            __syncthreads();
            if (dc < 6)
                attn_load_chunk(sb, dc & 1, g_kh, g_kl, srow0, dc + 2, tid);
            else
                attn_load_chunk(sb, dc & 1, g_vh, g_vl, srow0, dc - 6, tid);
        }

        // ---- softmax (each thread: rows 2ti,2ti+1 x cols 4tj..4tj+3) ----
        {
            float4 v0 = *(float4*)&S[(2 * ti) * SD + 4 * tj];
            float4 v1 = *(float4*)&S[(2 * ti + 1) * SD + 4 * tj];
            float a0[4] = {v0.x, v0.y, v0.z, v0.w};
            float a1[4] = {v1.x, v1.y, v1.z, v1.w};

            if (jb == jbmax) {
                int qi0 = qb * 32 + 2 * ti;
                int kj  = jb * 64 + 4 * tj;
#pragma unroll
                for (int c = 0; c < 4; c++) {
                    if (kj + c > qi0)     a0[c] = NEG_INF;
                    if (kj + c > qi0 + 1) a1[c] = NEG_INF;
                }
            }

            float r0 = fmaxf(fmaxf(a0[0], a0[1]), fmaxf(a0[2], a0[3]));
            float r1 = fmaxf(fmaxf(a1[0], a1[1]), fmaxf(a1[2], a1[3]));
#pragma unroll
            for (int off = 1; off < 16; off <<= 1) {
                r0 = fmaxf(r0, __shfl_xor_sync(0xffffffffu, r0, off));
                r1 = fmaxf(r1, __shfl_xor_sync(0xffffffffu, r1, off));
            }
            float mn0 = fmaxf(m0r, r0);
            float mn1 = fmaxf(m1r, r1);
            float al0 = __expf(m0r - mn0);
            float al1 = __expf(m1r - mn1);

            float p0[4], p1[4];
#pragma unroll
            for (int c = 0; c < 4; c++) {
                p0[c] = __expf(a0[c] - mn0);
                p1[c] = __expf(a1[c] - mn1);
            }
            float rs0 = (p0[0] + p0[1]) + (p0[2] + p0[3]);
            float rs1 = (p1[0] + p1[1]) + (p1[2] + p1[3]);
#pragma unroll
            for (int off = 1; off < 16; off <<= 1) {
                rs0 += __shfl_xor_sync(0xffffffffu, rs0, off);
                rs1 += __shfl_xor_sync(0xffffffffu, rs1, off);
            }
            l0r = al0 * l0r + rs0;  m0r = mn0;
            l1r = al1 * l1r + rs1;  m1r = mn1;

            if (tj == 0) {
                AL[2 * ti]     = al0;
                AL[2 * ti + 1] = al1;
                LL[2 * ti]     = l0r;
                LL[2 * ti + 1] = l1r;
            }
            __syncthreads();   // all S reads done before P overlays S

            __nv_bfloat16 h0[4], h1[4];
#pragma unroll
            for (int c = 0; c < 4; c++) {
                h0[c] = __float2bfloat16(p0[c]);
                h1[c] = __float2bfloat16(p1[c]);
            }
            *(__nv_bfloat162*)&PH[(2 * ti) * PP + 4 * tj]         = __nv_bfloat162(h0[0], h0[1]);
            *(__nv_bfloat162*)&PH[(2 * ti) * PP + 4 * tj + 2]     = __nv_bfloat162(h0[2], h0[3]);
            *(__nv_bfloat162*)&PH[(2 * ti + 1) * PP + 4 * tj]     = __nv_bfloat162(h1[0], h1[1]);
            *(__nv_bfloat162*)&PH[(2 * ti + 1) * PP + 4 * tj + 2] = __nv_bfloat162(h1[2], h1[3]);
            *(__nv_bfloat162*)&PL[(2 * ti) * PP + 4 * tj] = __nv_bfloat162(
                __float2bfloat16(p0[0] - __bfloat162float(h0[0])),
                __float2bfloat16(p0[1] - __bfloat162float(h0[1])));
            *(__nv_bfloat162*)&PL[(2 * ti) * PP + 4 * tj + 2] = __nv_bfloat162(
                __float2bfloat16(p0[2] - __bfloat162float(h0[2])),
                __float2bfloat16(p0[3] - __bfloat162float(h0[3])));
            *(__nv_bfloat162*)&PL[(2 * ti + 1) * PP + 4 * tj] = __nv_bfloat162(
                __float2bfloat16(p1[0] - __bfloat162float(h1[0])),
                __float2bfloat16(p1[1] - __bfloat162float(h1[1])));
            *(__nv_bfloat162*)&PL[(2 * ti + 1) * PP + 4 * tj + 2] = __nv_bfloat162(
                __float2bfloat16(p1[2] - __bfloat162float(h1[2])),
                __float2bfloat16(p1[3] - __bfloat162float(h1[3])));
        }
        __syncthreads();   // P + AL visible

        // hoist P fragments (whole 64-key tile) into registers
        unsigned Phf[4][4], Plf[4][4];
#pragma unroll
        for (int ks2 = 0; ks2 < 4; ks2++) {
            unsigned pcol = (ks2 * 16 + psel) * 2;
            ldsm4(Phf[ks2], sb + OPH + prow_a * 144 + pcol);
            ldsm4(Plf[ks2], sb + OPL + prow_a * 144 + pcol);
        }

        // scale accumulators by alpha
        {
            float a0 = AL[rh * 16 + (lane >> 2)];
            float a1 = AL[rh * 16 + (lane >> 2) + 8];
#pragma unroll
            for (int d = 0; d < 8; d++)
#pragma unroll
                for (int nt = 0; nt < 2; nt++) {
                    acc[d][nt][0] *= a0; acc[d][nt][1] *= a0;
                    acc[d][nt][2] *= a1; acc[d][nt][3] *= a1;
                }
        }

        // ---- PV phase over 8 streamed V d-chunks ----
#pragma unroll
        for (int dc = 0; dc < 8; dc++) {
            if (last && dc == 7) cp_wait<0>(); else cp_wait<1>();
            __syncthreads();
            unsigned vb = sb + OCB + (dc & 1) * 18432;
#pragma unroll
            for (int ks2 = 0; ks2 < 4; ks2++) {
                unsigned vrow = (ks2 * 16 + vsrow) * 144;
                unsigned vcol = (vg * 16 + vdoff) * 2;
                unsigned Bh[4], Bl[4];
                ldsm4t(Bh, vb + vrow + vcol);
                ldsm4t(Bl, vb + 9216 + vrow + vcol);
                mma_bf16(acc[dc][0], Phf[ks2], Bh[0], Bh[1]);
                mma_bf16(acc[dc][0], Plf[ks2], Bh[0], Bh[1]);
                mma_bf16(acc[dc][0], Phf[ks2], Bl[0], Bl[1]);
                mma_bf16(acc[dc][1], Phf[ks2], Bh[2], Bh[3]);
                mma_bf16(acc[dc][1], Plf[ks2], Bh[2], Bh[3]);
                mma_bf16(acc[dc][1], Phf[ks2], Bl[2], Bl[3]);
            }
            __syncthreads();
            if (dc < 6)
                attn_load_chunk(sb, dc & 1, g_vh, g_vl, srow0, dc + 2, tid);
            else if (!last)
                attn_load_chunk(sb, dc & 1, g_kh, g_kl, srow0 + 64, dc - 6, tid);
        }
    }

    // ---- epilogue: 1/l, LayerNorm, store ----
    {
        int r  = lane >> 2;
        int c2 = (lane & 3) * 2;
        int row0 = rh * 16 + r;
        int row1 = row0 + 8;
        float linv0 = 1.0f / LL[row0];
        float linv1 = 1.0f / LL[row1];
        float s0 = 0.f, q0 = 0.f, s1 = 0.f, q1 = 0.f;
#pragma unroll
        for (int d = 0; d < 8; d++)
#pragma unroll
            for (int nt = 0; nt < 2; nt++) {
                acc[d][nt][0] *= linv0; acc[d][nt][1] *= linv0;
                acc[d][nt][2] *= linv1; acc[d][nt][3] *= linv1;
                s0 += acc[d][nt][0] + acc[d][nt][1];
                q0 += acc[d][nt][0] * acc[d][nt][0] + acc[d][nt][1] * acc[d][nt][1];
                s1 += acc[d][nt][2] + acc[d][nt][3];
                q1 += acc[d][nt][2] * acc[d][nt][2] + acc[d][nt][3] * acc[d][nt][3];
            }
#pragma unroll
        for (int off = 1; off < 4; off <<= 1) {
            s0 += __shfl_xor_sync(0xffffffffu, s0, off);
            q0 += __shfl_xor_sync(0xffffffffu, q0, off);
            s1 += __shfl_xor_sync(0xffffffffu, s1, off);
            q1 += __shfl_xor_sync(0xffffffffu, q1, off);
        }
        if ((lane & 3) == 0) {
            RS[row0 * 4 + vg] = s0;  RQ[row0 * 4 + vg] = q0;
            RS[row1 * 4 + vg] = s1;  RQ[row1 * 4 + vg] = q1;
        }
        __syncthreads();
        float ts0 = RS[row0 * 4] + RS[row0 * 4 + 1] + RS[row0 * 4 + 2] + RS[row0 * 4 + 3];
        float tq0 = RQ[row0 * 4] + RQ[row0 * 4 + 1] + RQ[row0 * 4 + 2] + RQ[row0 * 4 + 3];
        float ts1 = RS[row1 * 4] + RS[row1 * 4 + 1] + RS[row1 * 4 + 2] + RS[row1 * 4 + 3];
        float tq1 = RQ[row1 * 4] + RQ[row1 * 4 + 1] + RQ[row1 * 4 + 2] + RQ[row1 * 4 + 3];
        const float invD = 1.0f / (float)DIM;
        float mu0 = ts0 * invD, var0 = tq0 * invD - mu0 * mu0;
        float mu1 = ts1 * invD, var1 = tq1 * invD - mu1 * mu1;
        float rstd0 = rsqrtf(var0 + 1e-5f);
        float rstd1 = rsqrtf(var1 + 1e-5f);

        size_t ob0 = (qrow0 + row0) * 512;
        size_t ob1 = (qrow0 + row1) * 512;
#pragma unroll
        for (int d = 0; d < 8; d++)
#pragma unroll
            for (int nt = 0; nt < 2; nt++) {
                int col = d * 64 + vg * 16 + nt * 8 + c2;
                float g0 = gamma[col], g1 = gamma[col + 1];
                float be0 = beta[col], be1 = beta[col + 1];
                float2 o0 = make_float2((acc[d][nt][0] - mu0) * rstd0 * g0 + be0,
                                        (acc[d][nt][1] - mu0) * rstd0 * g1 + be1);
                float2 o1 = make_float2((acc[d][nt][2] - mu1) * rstd1 * g0 + be0,
                                        (acc[d][nt][3] - mu1) * rstd1 * g1 + be1);
                *(float2*)(out + ob0 + col) = o0;
                *(float2*)(out + ob1 + col) = o1;
            }
    }
}

// ---------------------------------------------------------------------------
// Launch
// ---------------------------------------------------------------------------
extern "C" void kernel_launch(void* const* d_in, const int* in_sizes, int n_in,
                              void* d_out, int out_size)
{
    const float* x0    = (const float*)d_in[0];
    const float* x1    = (const float*)d_in[1];
    const float* Wq    = (const float*)d_in[2];
    const float* Wk    = (const float*)d_in[3];
    const float* Wv    = (const float*)d_in[4];
    const float* gamma = (const float*)d_in[5];
    const float* beta  = (const float*)d_in[6];
    float* out = (float*)d_out;

    cudaFuncSetAttribute(qkv_hmma, cudaFuncAttributeMaxDynamicSharedMemorySize, GB_SMEM);
    cudaFuncSetAttribute(attn_mma, cudaFuncAttributeMaxDynamicSharedMemorySize, ATTN_SMEM);

    conv_x<<<MTOT, 256>>>(x0, x1);
    conv_w<<<dim3(16, 32, 3), dim3(32, 8)>>>(Wq, Wk, Wv);
    qkv_hmma<<<dim3(12, 128), 256, GB_SMEM>>>();
    attn_mma<<<dim3(SEQ / 32, BATCH), 256, ATTN_SMEM>>>(gamma, beta, out);
}